// round 10
// baseline (speedup 1.0000x reference)
#include <cuda_runtime.h>
#include <cuda_bf16.h>
#include <math.h>
#include <stdint.h>

#define NN 20000
#define NE 320000
#define NG 32
#define CC 256
#define NL 4
#define INDIM 739
#define KXP 768            // padded input K (mult of 64)
#define EDIM 518
#define LNEPS 1e-5f
__device__ __constant__ float INV_ED = 1.0f / 518.0f;

// ---------------- scratch (device globals; no allocation allowed) ----------
__device__ float g_h[NN * CC];
__device__ float g_m[NN * CC];
__device__ __nv_bfloat16 g_xhi[NN * KXP];
__device__ __nv_bfloat16 g_xlo[NN * KXP];
__device__ __nv_bfloat16 g_hhi[NN * CC];
__device__ __nv_bfloat16 g_hlo[NN * CC];
__device__ __nv_bfloat16 g_aghi[NN * CC];
__device__ __nv_bfloat16 g_aglo[NN * CC];
// weight table (transposed [N][K], split): dense 256x768, then 8x 256x256
#define WT_DENSE 0
#define WT_SZ (256 * KXP + 8 * 256 * 256)
__device__ __nv_bfloat16 g_wthi[WT_SZ];
__device__ __nv_bfloat16 g_wtlo[WT_SZ];
__device__ float g_S[NN];
__device__ float g_Q[NN];
__device__ float4 g_us[NN];
__device__ float4 g_ud[NN];
__device__ float4 g_gw4[NL * EDIM];
__device__ float g_c0[NL * 4];
__device__ float g_c1[NL * 4];
__device__ int g_cnt[NN];
__device__ int g_rowptr[NN + 1];
__device__ int g_cursor[NN];
__device__ int g_csrc[NE];
__device__ int g_bsum[32];
__device__ float g_pool[NG];
__device__ int g_gcnt[NG];

__device__ __forceinline__ float gelu_f(float x) {
    return 0.5f * x * (1.0f + erff(x * 0.70710678118654752f));
}

__device__ __forceinline__ uint32_t smem_to_u32(const void* p) {
    uint32_t a;
    asm("{ .reg .u64 t; cvta.to.shared.u64 t, %1; cvt.u32.u64 %0, t; }"
        : "=r"(a) : "l"(p));
    return a;
}

#define LDSM4(r, addr) \
    asm volatile("ldmatrix.sync.aligned.m8n8.x4.shared.b16 {%0,%1,%2,%3}, [%4];" \
        : "=r"((r)[0]), "=r"((r)[1]), "=r"((r)[2]), "=r"((r)[3]) : "r"(addr))
#define MMA16816(d, a, b) \
    asm volatile("mma.sync.aligned.m16n8k16.row.col.f32.bf16.bf16.f32 " \
        "{%0,%1,%2,%3}, {%4,%5,%6,%7}, {%8,%9}, {%0,%1,%2,%3};" \
        : "+f"((d)[0]), "+f"((d)[1]), "+f"((d)[2]), "+f"((d)[3]) \
        : "r"((a)[0]), "r"((a)[1]), "r"((a)[2]), "r"((a)[3]), \
          "r"((b)[0]), "r"((b)[1]))
#define CP_ASYNC16(sm, gp) \
    asm volatile("cp.async.cg.shared.global [%0], [%1], 16;" :: "r"(sm), "l"(gp))
#define CP_COMMIT() asm volatile("cp.async.commit_group;" ::: "memory")
#define CP_WAIT(n)  asm volatile("cp.async.wait_group %0;" :: "n"(n) : "memory")

// ---------------- misc small kernels ---------------------------------------
__global__ void zero_kernel() {
    int i = blockIdx.x * blockDim.x + threadIdx.x;
    if (i < NN) g_cnt[i] = 0;
    if (i < NG) { g_gcnt[i] = 0; g_pool[i] = 0.0f; }
}
__global__ void hist_kernel(const int* __restrict__ dst) {
    int e = blockIdx.x * blockDim.x + threadIdx.x;
    if (e < NE) atomicAdd(&g_cnt[dst[e]], 1);
}
__global__ void bhist_kernel(const int* __restrict__ batch) {
    int i = blockIdx.x * blockDim.x + threadIdx.x;
    if (i < NN) atomicAdd(&g_gcnt[batch[i]], 1);
}
__global__ void scan1_kernel() {
    __shared__ int s[1024];
    int t = threadIdx.x, b = blockIdx.x;
    int i = b * 1024 + t;
    int v = (i < NN) ? g_cnt[i] : 0;
    s[t] = v;
    __syncthreads();
    #pragma unroll
    for (int off = 1; off < 1024; off <<= 1) {
        int x = (t >= off) ? s[t - off] : 0;
        __syncthreads();
        s[t] += x;
        __syncthreads();
    }
    if (i < NN) g_rowptr[i] = s[t] - v;
    if (t == 1023) g_bsum[b] = s[1023];
}
__global__ void scan2_kernel() {
    int run = 0;
    for (int b = 0; b < 20; b++) { int t = g_bsum[b]; g_bsum[b] = run; run += t; }
    g_rowptr[NN] = run;
}
__global__ void scan3_kernel() {
    int i = blockIdx.x * blockDim.x + threadIdx.x;
    if (i < NN) {
        int r = g_rowptr[i] + g_bsum[i >> 10];
        g_rowptr[i] = r;
        g_cursor[i] = r;
    }
}
__global__ void fill_kernel(const int* __restrict__ src, const int* __restrict__ dst) {
    int e = blockIdx.x * blockDim.x + threadIdx.x;
    if (e < NE) {
        int d = dst[e];
        int p = atomicAdd(&g_cursor[d], 1);
        g_csrc[p] = src[e];
    }
}

// ---------------- conversion kernels ----------------------------------------
__global__ void conv_x_kernel(const float* __restrict__ x) {
    int i = blockIdx.x * blockDim.x + threadIdx.x;
    if (i >= NN * KXP) return;
    int n = i / KXP, k = i - n * KXP;
    float v = (k < INDIM) ? x[(size_t)n * INDIM + k] : 0.0f;
    __nv_bfloat16 hi = __float2bfloat16(v);
    g_xhi[i] = hi;
    g_xlo[i] = __float2bfloat16(v - __bfloat162float(hi));
}
__global__ void conv_w_kernel(const float* __restrict__ dense_w,
                              const float* __restrict__ d1_w,
                              const float* __restrict__ d2_w) {
    int i = blockIdx.x * blockDim.x + threadIdx.x;
    if (i >= WT_SZ) return;
    float v;
    if (i < 256 * KXP) {
        int n = i / KXP, k = i - n * KXP;
        v = (k < INDIM) ? dense_w[(size_t)k * 256 + n] : 0.0f;
    } else {
        int j = i - 256 * KXP;
        int mat = j >> 16;            // 0..7
        int r = j & 65535;
        int n = r >> 8, k = r & 255;
        int l = mat >> 1;
        const float* w = (mat & 1) ? d2_w : d1_w;
        v = w[(size_t)l * 65536 + k * 256 + n];
    }
    __nv_bfloat16 hi = __float2bfloat16(v);
    g_wthi[i] = hi;
    g_wtlo[i] = __float2bfloat16(v - __bfloat162float(hi));
}

// ---------------- split-bf16 mma.sync GEMM, cp.async 2-stage -----------------
// C[M,256] = act(A @ B^T + bias); tiles 128x128, 4 warps of 64x64, K chunks 32.
#define SROW 80                       // 64B data + 16B pad, conflict-free ldmatrix
#define TTILE (128 * SROW)            // 10240 bytes per (tile,split)
#define STAGE_B (4 * TTILE)           // 40960 bytes per stage
#define GEMM_SMEM (2 * STAGE_B)       // 81920

__device__ __forceinline__ void prefetch_chunk(uint32_t sb, int stage,
        const __nv_bfloat16* __restrict__ Ahi, const __nv_bfloat16* __restrict__ Alo,
        const __nv_bfloat16* __restrict__ Bhi, const __nv_bfloat16* __restrict__ Blo,
        int row0, int M, int kst, int k0) {
    int tid = threadIdx.x;
    uint32_t base = sb + stage * STAGE_B;
    // per tile: 128 rows x 4 granules(16B) = 512 loads / 128 threads = 4 each
    #pragma unroll
    for (int it = 0; it < 4; it++) {
        int g = tid + it * 128;
        int r = g >> 2;
        int gc = g & 3;
        uint32_t soff = (uint32_t)(r * SROW + gc * 16);
        int ra = row0 + r; ra = (ra < M) ? ra : 0;
        size_t aoff = (size_t)ra * kst + k0 + gc * 8;
        CP_ASYNC16(base + soff,             Ahi + aoff);
        CP_ASYNC16(base + TTILE + soff,     Alo + aoff);
        size_t boff = (size_t)r * kst + k0 + gc * 8;   // B rows 0..127 all valid
        CP_ASYNC16(base + 2 * TTILE + soff, Bhi + boff);
        CP_ASYNC16(base + 3 * TTILE + soff, Blo + boff);
    }
}

__global__ void __launch_bounds__(128, 2) gemm_mma_kernel(
    const __nv_bfloat16* __restrict__ Ahi, const __nv_bfloat16* __restrict__ Alo,
    const __nv_bfloat16* __restrict__ Bhi, const __nv_bfloat16* __restrict__ Blo,
    const float* __restrict__ bias, float* __restrict__ outf,
    __nv_bfloat16* __restrict__ outhi, __nv_bfloat16* __restrict__ outlo,
    int M, int kst, int nc, int act)
{
    extern __shared__ char smem[];
    int tid = threadIdx.x;
    int w = tid >> 5, l = tid & 31;
    int row0 = blockIdx.y * 128, col0 = blockIdx.x * 128;
    int wm = (w & 1) * 64;            // warp row offset (64-row tile)
    int wn = (w >> 1) * 64;           // warp col offset (64-col tile)
    const __nv_bfloat16* Bh = Bhi + (size_t)col0 * kst;
    const __nv_bfloat16* Bl = Blo + (size_t)col0 * kst;

    float acc[4][8][4];
    #pragma unroll
    for (int mt = 0; mt < 4; mt++)
        #pragma unroll
        for (int nt = 0; nt < 8; nt++)
            #pragma unroll
            for (int q = 0; q < 4; q++) acc[mt][nt][q] = 0.0f;

    uint32_t sbase = smem_to_u32(smem);
    // A ldmatrix.x4 lane address: rows wm + mt*16 + (l&15), col half (l>>4)*16
    uint32_t a_lrow = (uint32_t)(wm + (l & 15));
    uint32_t a_lcol = (uint32_t)((l >> 4) * 16);
    // B ldmatrix.x4 covers 2 nt: rows wn + pair*16 + ((l>>4)&1)*8 + (l&7),
    // col half ((l>>3)&1)*16
    uint32_t b_lrow = (uint32_t)(wn + ((l >> 4) & 1) * 8 + (l & 7));
    uint32_t b_lcol = (uint32_t)(((l >> 3) & 1) * 16);

    prefetch_chunk(sbase, 0, Ahi, Alo, Bh, Bl, row0, M, kst, 0);
    CP_COMMIT();

    for (int c = 0; c < nc; c++) {
        if (c + 1 < nc) {
            prefetch_chunk(sbase, (c + 1) & 1, Ahi, Alo, Bh, Bl, row0, M, kst, (c + 1) * 32);
            CP_COMMIT();
            CP_WAIT(1);
        } else {
            CP_WAIT(0);
        }
        __syncthreads();
        uint32_t stb = sbase + (c & 1) * STAGE_B;
        #pragma unroll
        for (int kk = 0; kk < 2; kk++) {
            uint32_t ah[4][4], al[4][4], bh[4][4], bl[4][4];
            #pragma unroll
            for (int mt = 0; mt < 4; mt++) {
                uint32_t off = (a_lrow + mt * 16) * SROW + kk * 32 + a_lcol;
                LDSM4(ah[mt], stb + off);
                LDSM4(al[mt], stb + TTILE + off);
            }
            #pragma unroll
            for (int pr = 0; pr < 4; pr++) {          // nt pair = {2pr, 2pr+1}
                uint32_t off = (b_lrow + pr * 16) * SROW + kk * 32 + b_lcol;
                LDSM4(bh[pr], stb + 2 * TTILE + off);
                LDSM4(bl[pr], stb + 3 * TTILE + off);
            }
            #pragma unroll
            for (int pr = 0; pr < 4; pr++) {
                #pragma unroll
                for (int sub = 0; sub < 2; sub++) {
                    int nt = 2 * pr + sub;
                    uint32_t* bhf = &bh[pr][2 * sub];
                    uint32_t* blf = &bl[pr][2 * sub];
                    #pragma unroll
                    for (int mt = 0; mt < 4; mt++) {
                        MMA16816(acc[mt][nt], ah[mt], bhf);
                        MMA16816(acc[mt][nt], ah[mt], blf);
                        MMA16816(acc[mt][nt], al[mt], bhf);
                    }
                }
            }
        }
        __syncthreads();
    }

    // epilogue: bias + (gelu) + f32 store + optional split-bf16 store
    int gid = l >> 2, tig = l & 3;
    #pragma unroll
    for (int mt = 0; mt < 4; mt++) {
        #pragma unroll
        for (int half = 0; half < 2; half++) {
            int gr = row0 + wm + mt * 16 + gid + half * 8;
            if (gr >= M) continue;
            #pragma unroll
            for (int nt = 0; nt < 8; nt++) {
                int gc = col0 + wn + nt * 8 + 2 * tig;
                float v0 = acc[mt][nt][2 * half + 0] + bias[gc];
                float v1 = acc[mt][nt][2 * half + 1] + bias[gc + 1];
                if (act) { v0 = gelu_f(v0); v1 = gelu_f(v1); }
                size_t ro = (size_t)gr * 256 + gc;
                *reinterpret_cast<float2*>(outf + ro) = make_float2(v0, v1);
                if (outhi) {
                    __nv_bfloat16 h0 = __float2bfloat16(v0);
                    __nv_bfloat16 h1 = __float2bfloat16(v1);
                    __nv_bfloat162 h2; h2.x = h0; h2.y = h1;
                    __nv_bfloat162 l2;
                    l2.x = __float2bfloat16(v0 - __bfloat162float(h0));
                    l2.y = __float2bfloat16(v1 - __bfloat162float(h1));
                    *reinterpret_cast<__nv_bfloat162*>(outhi + ro) = h2;
                    *reinterpret_cast<__nv_bfloat162*>(outlo + ro) = l2;
                }
            }
        }
    }
}

// ---------------- per-layer constants (all layers, data-independent) --------
__global__ void const_all_kernel(
    const float* __restrict__ ln1g, const float* __restrict__ ln1b,
    const float* __restrict__ w1w, const float* __restrict__ w1b)
{
    __shared__ float c0s[4], c1s[4];
    int lyr = blockIdx.x;
    int t = threadIdx.x;
    const float* lg = ln1g + lyr * EDIM;
    const float* lb = ln1b + lyr * EDIM;
    const float* ww = w1w + (size_t)lyr * EDIM * 4;
    if (t < 4) { c0s[t] = 0.0f; c1s[t] = 0.0f; }
    __syncthreads();
    if (t < EDIM) {
        float g = lg[t], bb = lb[t];
        float w0 = ww[t * 4 + 0], w1 = ww[t * 4 + 1];
        float w2 = ww[t * 4 + 2], w3 = ww[t * 4 + 3];
        g_gw4[lyr * EDIM + t] = make_float4(g * w0, g * w1, g * w2, g * w3);
        atomicAdd(&c1s[0], g * w0); atomicAdd(&c1s[1], g * w1);
        atomicAdd(&c1s[2], g * w2); atomicAdd(&c1s[3], g * w3);
        atomicAdd(&c0s[0], bb * w0); atomicAdd(&c0s[1], bb * w1);
        atomicAdd(&c0s[2], bb * w2); atomicAdd(&c0s[3], bb * w3);
    }
    __syncthreads();
    if (t < 4) {
        g_c0[lyr * 4 + t] = c0s[t] + w1b[lyr * 4 + t];
        g_c1[lyr * 4 + t] = c1s[t];
    }
}

// ---------------- per-node stats --------------------------------------------
__global__ void __launch_bounds__(256) node_stats_kernel(const float* __restrict__ xpos, int lyr) {
    int n = (blockIdx.x * blockDim.x + threadIdx.x) >> 5;
    int lane = threadIdx.x & 31;
    if (n >= NN) return;
    const float* mr = g_m + (size_t)n * CC;
    const float4* gw = g_gw4 + lyr * EDIM;
    float s = 0, q = 0;
    float us0 = 0, us1 = 0, us2 = 0, us3 = 0;
    float ud0 = 0, ud1 = 0, ud2 = 0, ud3 = 0;
    #pragma unroll
    for (int j = 0; j < 8; j++) {
        int c = lane + j * 32;
        float v = mr[c];
        s += v; q = fmaf(v, v, q);
        float4 gs = gw[c];
        float4 gd = gw[CC + c];
        us0 = fmaf(v, gs.x, us0); us1 = fmaf(v, gs.y, us1);
        us2 = fmaf(v, gs.z, us2); us3 = fmaf(v, gs.w, us3);
        ud0 = fmaf(v, gd.x, ud0); ud1 = fmaf(v, gd.y, ud1);
        ud2 = fmaf(v, gd.z, ud2); ud3 = fmaf(v, gd.w, ud3);
    }
    if (lane < 3) {
        float p = xpos[n * 3 + lane];
        s += p; q = fmaf(p, p, q);
        float4 gs = gw[2 * CC + lane];
        float4 gd = gw[2 * CC + 3 + lane];
        us0 = fmaf(p, gs.x, us0); us1 = fmaf(p, gs.y, us1);
        us2 = fmaf(p, gs.z, us2); us3 = fmaf(p, gs.w, us3);
        ud0 = fmaf(p, gd.x, ud0); ud1 = fmaf(p, gd.y, ud1);
        ud2 = fmaf(p, gd.z, ud2); ud3 = fmaf(p, gd.w, ud3);
    }
    #pragma unroll
    for (int off = 16; off; off >>= 1) {
        s   += __shfl_xor_sync(0xffffffffu, s, off);
        q   += __shfl_xor_sync(0xffffffffu, q, off);
        us0 += __shfl_xor_sync(0xffffffffu, us0, off);
        us1 += __shfl_xor_sync(0xffffffffu, us1, off);
        us2 += __shfl_xor_sync(0xffffffffu, us2, off);
        us3 += __shfl_xor_sync(0xffffffffu, us3, off);
        ud0 += __shfl_xor_sync(0xffffffffu, ud0, off);
        ud1 += __shfl_xor_sync(0xffffffffu, ud1, off);
        ud2 += __shfl_xor_sync(0xffffffffu, ud2, off);
        ud3 += __shfl_xor_sync(0xffffffffu, ud3, off);
    }
    if (lane == 0) {
        g_S[n] = s; g_Q[n] = q;
        g_us[n] = make_float4(us0, us1, us2, us3);
        g_ud[n] = make_float4(ud0, ud1, ud2, ud3);
    }
}

// ---------------- aggregation ------------------------------------------------
__global__ void __launch_bounds__(256) aggregate_kernel(
    const float* __restrict__ ln2g, const float* __restrict__ ln2b,
    const float* __restrict__ w2w, const float* __restrict__ w2b, int lyr)
{
    int n = blockIdx.x;
    int tid = threadIdx.x;
    __shared__ float ws[128];
    __shared__ int ss[128];
    __shared__ float nc[6];
    const float* c0 = g_c0 + lyr * 4;
    const float* c1 = g_c1 + lyr * 4;
    int beg = g_rowptr[n], end = g_rowptr[n + 1];
    if (tid == 0) {
        nc[0] = g_S[n]; nc[1] = g_Q[n];
        float4 u = g_ud[n];
        nc[2] = u.x; nc[3] = u.y; nc[4] = u.z; nc[5] = u.w;
    }
    __syncthreads();
    float acc = 0.0f;
    for (int e0 = beg; e0 < end; e0 += 128) {
        int cnt = min(128, end - e0);
        if (tid < cnt) {
            int srcn = g_csrc[e0 + tid];
            float4 us = g_us[srcn];
            float mu = (g_S[srcn] + nc[0]) * INV_ED;
            float var = fmaf(-mu, mu, (g_Q[srcn] + nc[1]) * INV_ED);
            float rs = rsqrtf(var + LNEPS);
            float t0 = gelu_f(fmaf(rs, (us.x + nc[2]) - mu * c1[0], c0[0]));
            float t1 = gelu_f(fmaf(rs, (us.y + nc[3]) - mu * c1[1], c0[1]));
            float t2 = gelu_f(fmaf(rs, (us.z + nc[4]) - mu * c1[2], c0[2]));
            float t3 = gelu_f(fmaf(rs, (us.w + nc[5]) - mu * c1[3], c0[3]));
            float mu2 = 0.25f * (t0 + t1 + t2 + t3);
            float d0 = t0 - mu2, d1 = t1 - mu2, d2 = t2 - mu2, d3 = t3 - mu2;
            float var2 = 0.25f * (d0 * d0 + d1 * d1 + d2 * d2 + d3 * d3);
            float rs2 = rsqrtf(var2 + LNEPS);
            float z = (fmaf(d0 * rs2, ln2g[0], ln2b[0])) * w2w[0]
                    + (fmaf(d1 * rs2, ln2g[1], ln2b[1])) * w2w[1]
                    + (fmaf(d2 * rs2, ln2g[2], ln2b[2])) * w2w[2]
                    + (fmaf(d3 * rs2, ln2g[3], ln2b[3])) * w2w[3] + w2b[0];
            ws[tid] = 1.0f / (1.0f + expf(-z));
            ss[tid] = srcn;
        }
        __syncthreads();
        #pragma unroll 4
        for (int i = 0; i < cnt; i++)
            acc = fmaf(g_m[(size_t)ss[i] * CC + tid], ws[i], acc);
        __syncthreads();
    }
    size_t o = (size_t)n * CC + tid;
    __nv_bfloat16 hi = __float2bfloat16(acc);
    g_aghi[o] = hi;
    g_aglo[o] = __float2bfloat16(acc - __bfloat162float(hi));
}

// ---------------- pooling + head --------------------------------------------
__global__ void __launch_bounds__(256) pool_kernel(
    const int* __restrict__ batch, const float* __restrict__ head_w)
{
    int n = (blockIdx.x * blockDim.x + threadIdx.x) >> 5;
    int lane = threadIdx.x & 31;
    if (n >= NN) return;
    const float* hr = g_h + (size_t)n * CC;
    float s = 0;
    #pragma unroll
    for (int j = 0; j < 8; j++)
        s = fmaf(hr[lane + j * 32], head_w[lane + j * 32], s);
    #pragma unroll
    for (int off = 16; off; off >>= 1)
        s += __shfl_xor_sync(0xffffffffu, s, off);
    if (lane == 0) atomicAdd(&g_pool[batch[n]], s);
}
__global__ void final_kernel(float* __restrict__ out, const float* __restrict__ head_b) {
    int g = threadIdx.x;
    if (g < NG)
        out[g] = g_pool[g] / fmaxf((float)g_gcnt[g], 1.0f) + head_b[0];
}

// ---------------- launch -----------------------------------------------------
extern "C" void kernel_launch(void* const* d_in, const int* in_sizes, int n_in,
                              void* d_out, int out_size)
{
    const float* x       = (const float*)d_in[0];
    const float* xpos    = (const float*)d_in[1];
    const int*   ei      = (const int*)  d_in[2];
    const int*   batch   = (const int*)  d_in[3];
    const float* dense_w = (const float*)d_in[4];
    const float* dense_b = (const float*)d_in[5];
    const float* d1_w    = (const float*)d_in[6];
    const float* d1_b    = (const float*)d_in[7];
    const float* ln1_g   = (const float*)d_in[8];
    const float* ln1_b   = (const float*)d_in[9];
    const float* w1_w    = (const float*)d_in[10];
    const float* w1_b    = (const float*)d_in[11];
    const float* ln2_g   = (const float*)d_in[12];
    const float* ln2_b   = (const float*)d_in[13];
    const float* w2_w    = (const float*)d_in[14];
    const float* w2_b    = (const float*)d_in[15];
    const float* d2_w    = (const float*)d_in[16];
    const float* d2_b    = (const float*)d_in[17];
    const float* head_w  = (const float*)d_in[18];
    const float* head_b  = (const float*)d_in[19];

    const int* src = ei;
    const int* dst = ei + NE;

    cudaFuncSetAttribute(gemm_mma_kernel, cudaFuncAttributeMaxDynamicSharedMemorySize, GEMM_SMEM);

    float* p_h;  cudaGetSymbolAddress((void**)&p_h,  g_h);
    float* p_m;  cudaGetSymbolAddress((void**)&p_m,  g_m);
    __nv_bfloat16 *p_xhi, *p_xlo, *p_hhi, *p_hlo, *p_aghi, *p_aglo, *p_wthi, *p_wtlo;
    cudaGetSymbolAddress((void**)&p_xhi, g_xhi);
    cudaGetSymbolAddress((void**)&p_xlo, g_xlo);
    cudaGetSymbolAddress((void**)&p_hhi, g_hhi);
    cudaGetSymbolAddress((void**)&p_hlo, g_hlo);
    cudaGetSymbolAddress((void**)&p_aghi, g_aghi);
    cudaGetSymbolAddress((void**)&p_aglo, g_aglo);
    cudaGetSymbolAddress((void**)&p_wthi, g_wthi);
    cudaGetSymbolAddress((void**)&p_wtlo, g_wtlo);

    dim3 ggrid(2, (NN + 127) / 128);

    // conversions + consts + first GEMMs up front (GEMMs land in ncu window)
    conv_x_kernel<<<(NN * KXP + 255) / 256, 256>>>(x);
    conv_w_kernel<<<(WT_SZ + 255) / 256, 256>>>(dense_w, d1_w, d2_w);
    const_all_kernel<<<NL, 544>>>(ln1_g, ln1_b, w1_w, w1_b);
    gemm_mma_kernel<<<ggrid, 128, GEMM_SMEM>>>(
        p_xhi, p_xlo, p_wthi + WT_DENSE, p_wtlo + WT_DENSE,
        dense_b, p_h, p_hhi, p_hlo, NN, KXP, KXP / 32, 0);
    gemm_mma_kernel<<<ggrid, 128, GEMM_SMEM>>>(
        p_hhi, p_hlo, p_wthi + 256 * KXP, p_wtlo + 256 * KXP,
        d1_b, p_m, nullptr, nullptr, NN, CC, CC / 32, 1);
    node_stats_kernel<<<(NN * 32 + 255) / 256, 256>>>(xpos, 0);

    // CSR build + batch counts (needed before first aggregate)
    zero_kernel<<<(NN + 255) / 256, 256>>>();
    hist_kernel<<<(NE + 255) / 256, 256>>>(dst);
    scan1_kernel<<<20, 1024>>>();
    scan2_kernel<<<1, 1>>>();
    scan3_kernel<<<(NN + 255) / 256, 256>>>();
    fill_kernel<<<(NE + 255) / 256, 256>>>(src, dst);
    bhist_kernel<<<(NN + 255) / 256, 256>>>(batch);

    for (int l = 0; l < NL; l++) {
        size_t wd1 = (size_t)256 * KXP + (size_t)(2 * l) * 65536;
        size_t wd2 = (size_t)256 * KXP + (size_t)(2 * l + 1) * 65536;
        if (l > 0) {
            gemm_mma_kernel<<<ggrid, 128, GEMM_SMEM>>>(
                p_hhi, p_hlo, p_wthi + wd1, p_wtlo + wd1,
                d1_b + l * CC, p_m, nullptr, nullptr, NN, CC, CC / 32, 1);
            node_stats_kernel<<<(NN * 32 + 255) / 256, 256>>>(xpos, l);
        }
        aggregate_kernel<<<NN, 256>>>(ln2_g + l * 4, ln2_b + l * 4,
                                      w2_w + l * 4, w2_b + l, l);
        gemm_mma_kernel<<<ggrid, 128, GEMM_SMEM>>>(
            p_aghi, p_aglo, p_wthi + wd2, p_wtlo + wd2,
            d2_b + l * CC, p_h, p_hhi, p_hlo, NN, CC, CC / 32, 1);
    }

    pool_kernel<<<(NN * 32 + 255) / 256, 256>>>(batch, head_w);
    final_kernel<<<1, 32>>>((float*)d_out, head_b);
}

// round 12
// speedup vs baseline: 1.1117x; 1.1117x over previous
#include <cuda_runtime.h>
#include <cuda_bf16.h>
#include <math.h>
#include <stdint.h>

#define NN 20000
#define NE 320000
#define NG 32
#define CC 256
#define NL 4
#define INDIM 739
#define KXP 768            // padded input K (mult of 64)
#define EDIM 518
#define LNEPS 1e-5f
__device__ __constant__ float INV_ED = 1.0f / 518.0f;

// ---------------- scratch (device globals; no allocation allowed) ----------
__device__ float g_h[NN * CC];
__device__ float g_m[NN * CC];
__device__ __nv_bfloat16 g_xhi[NN * KXP];
__device__ __nv_bfloat16 g_xlo[NN * KXP];
__device__ __nv_bfloat16 g_hhi[NN * CC];
__device__ __nv_bfloat16 g_hlo[NN * CC];
__device__ __nv_bfloat16 g_aghi[NN * CC];
__device__ __nv_bfloat16 g_aglo[NN * CC];
// weight table (transposed [N][K], split): dense 256x768, then 8x 256x256
#define WT_DENSE 0
#define WT_SZ (256 * KXP + 8 * 256 * 256)
__device__ __nv_bfloat16 g_wthi[WT_SZ];
__device__ __nv_bfloat16 g_wtlo[WT_SZ];
__device__ float g_S[NN];
__device__ float g_Q[NN];
__device__ float4 g_us[NN];
__device__ float4 g_ud[NN];
__device__ float4 g_gw4[NL * EDIM];
__device__ float g_c0[NL * 4];
__device__ float g_c1[NL * 4];
__device__ int g_cnt[NN];
__device__ int g_rowptr[NN + 1];
__device__ int g_cursor[NN];
__device__ int g_csrc[NE];
__device__ int g_bsum[32];
__device__ float g_pool[NG];
__device__ int g_gcnt[NG];

__device__ __forceinline__ float gelu_f(float x) {
    return 0.5f * x * (1.0f + erff(x * 0.70710678118654752f));
}

__device__ __forceinline__ uint32_t smem_to_u32(const void* p) {
    uint32_t a;
    asm("{ .reg .u64 t; cvta.to.shared.u64 t, %1; cvt.u32.u64 %0, t; }"
        : "=r"(a) : "l"(p));
    return a;
}

#define LDSM4(r, addr) \
    asm volatile("ldmatrix.sync.aligned.m8n8.x4.shared.b16 {%0,%1,%2,%3}, [%4];" \
        : "=r"((r)[0]), "=r"((r)[1]), "=r"((r)[2]), "=r"((r)[3]) : "r"(addr))
#define MMA16816(d, a, b) \
    asm volatile("mma.sync.aligned.m16n8k16.row.col.f32.bf16.bf16.f32 " \
        "{%0,%1,%2,%3}, {%4,%5,%6,%7}, {%8,%9}, {%0,%1,%2,%3};" \
        : "+f"((d)[0]), "+f"((d)[1]), "+f"((d)[2]), "+f"((d)[3]) \
        : "r"((a)[0]), "r"((a)[1]), "r"((a)[2]), "r"((a)[3]), \
          "r"((b)[0]), "r"((b)[1]))
#define CP_ASYNC16(sm, gp) \
    asm volatile("cp.async.cg.shared.global [%0], [%1], 16;" :: "r"(sm), "l"(gp))
#define CP_COMMIT() asm volatile("cp.async.commit_group;" ::: "memory")
#define CP_WAIT(n)  asm volatile("cp.async.wait_group %0;" :: "n"(n) : "memory")

// ---------------- misc small kernels ---------------------------------------
__global__ void zero_kernel() {
    int i = blockIdx.x * blockDim.x + threadIdx.x;
    if (i < NN) g_cnt[i] = 0;
    if (i < NG) { g_gcnt[i] = 0; g_pool[i] = 0.0f; }
}
__global__ void hist2_kernel(const int* __restrict__ dst, const int* __restrict__ batch) {
    int e = blockIdx.x * blockDim.x + threadIdx.x;
    if (e < NE) atomicAdd(&g_cnt[dst[e]], 1);
    if (e < NN) atomicAdd(&g_gcnt[batch[e]], 1);
}
__global__ void scan1_kernel() {
    __shared__ int s[1024];
    int t = threadIdx.x, b = blockIdx.x;
    int i = b * 1024 + t;
    int v = (i < NN) ? g_cnt[i] : 0;
    s[t] = v;
    __syncthreads();
    #pragma unroll
    for (int off = 1; off < 1024; off <<= 1) {
        int x = (t >= off) ? s[t - off] : 0;
        __syncthreads();
        s[t] += x;
        __syncthreads();
    }
    if (i < NN) g_rowptr[i] = s[t] - v;
    if (t == 1023) g_bsum[b] = s[1023];
}
__global__ void scan2_kernel() {
    int run = 0;
    for (int b = 0; b < 20; b++) { int t = g_bsum[b]; g_bsum[b] = run; run += t; }
    g_rowptr[NN] = run;
}
__global__ void scan3_kernel() {
    int i = blockIdx.x * blockDim.x + threadIdx.x;
    if (i < NN) {
        int r = g_rowptr[i] + g_bsum[i >> 10];
        g_rowptr[i] = r;
        g_cursor[i] = r;
    }
}
__global__ void fill_kernel(const int* __restrict__ src, const int* __restrict__ dst) {
    int e = blockIdx.x * blockDim.x + threadIdx.x;
    if (e < NE) {
        int d = dst[e];
        int p = atomicAdd(&g_cursor[d], 1);
        g_csrc[p] = src[e];
    }
}

// ---------------- conversion kernels ----------------------------------------
__global__ void conv_x_kernel(const float* __restrict__ x) {
    int i = blockIdx.x * blockDim.x + threadIdx.x;
    if (i >= NN * KXP) return;
    int n = i / KXP, k = i - n * KXP;
    float v = (k < INDIM) ? x[(size_t)n * INDIM + k] : 0.0f;
    __nv_bfloat16 hi = __float2bfloat16(v);
    g_xhi[i] = hi;
    g_xlo[i] = __float2bfloat16(v - __bfloat162float(hi));
}
__global__ void conv_w_kernel(const float* __restrict__ dense_w,
                              const float* __restrict__ d1_w,
                              const float* __restrict__ d2_w) {
    int i = blockIdx.x * blockDim.x + threadIdx.x;
    if (i >= WT_SZ) return;
    float v;
    if (i < 256 * KXP) {
        int n = i / KXP, k = i - n * KXP;
        v = (k < INDIM) ? dense_w[(size_t)k * 256 + n] : 0.0f;
    } else {
        int j = i - 256 * KXP;
        int mat = j >> 16;            // 0..7
        int r = j & 65535;
        int n = r >> 8, k = r & 255;
        int l = mat >> 1;
        const float* w = (mat & 1) ? d2_w : d1_w;
        v = w[(size_t)l * 65536 + k * 256 + n];
    }
    __nv_bfloat16 hi = __float2bfloat16(v);
    g_wthi[i] = hi;
    g_wtlo[i] = __float2bfloat16(v - __bfloat162float(hi));
}

// ---------------- split-bf16 mma.sync GEMM, cp.async 4-stage -----------------
// C[M,256] = act(A @ B^T + bias); CTA tile 128x128, 8 warps of 32x64,
// K chunks of 16, 4-stage cp.async pipeline (prefetch distance 3).
#define SROW 48                       // 32B data + 16B pad, conflict-free ldmatrix
#define TTILE (128 * SROW)            // 6144 bytes per (tile,split)
#define STAGE_B (4 * TTILE)           // 24576 bytes per stage
#define NSTAGE 4
#define GEMM_SMEM (NSTAGE * STAGE_B)  // 98304

__device__ __forceinline__ void prefetch_chunk(uint32_t sb, int stage,
        const __nv_bfloat16* __restrict__ Ahi, const __nv_bfloat16* __restrict__ Alo,
        const __nv_bfloat16* __restrict__ Bhi, const __nv_bfloat16* __restrict__ Blo,
        int row0, int M, int kst, int k0) {
    int tid = threadIdx.x;
    uint32_t base = sb + stage * STAGE_B;
    // 128 rows x 2 granules(16B) = 256 slots = 1 per thread per tile
    int r = tid >> 1;
    int gc = tid & 1;
    uint32_t soff = (uint32_t)(r * SROW + gc * 16);
    int ra = row0 + r; ra = (ra < M) ? ra : 0;
    size_t aoff = (size_t)ra * kst + k0 + gc * 8;
    CP_ASYNC16(base + soff,             Ahi + aoff);
    CP_ASYNC16(base + TTILE + soff,     Alo + aoff);
    size_t boff = (size_t)r * kst + k0 + gc * 8;      // B rows 0..127 all valid
    CP_ASYNC16(base + 2 * TTILE + soff, Bhi + boff);
    CP_ASYNC16(base + 3 * TTILE + soff, Blo + boff);
}

__global__ void __launch_bounds__(256, 2) gemm_mma_kernel(
    const __nv_bfloat16* __restrict__ Ahi, const __nv_bfloat16* __restrict__ Alo,
    const __nv_bfloat16* __restrict__ Bhi, const __nv_bfloat16* __restrict__ Blo,
    const float* __restrict__ bias, float* __restrict__ outf,
    __nv_bfloat16* __restrict__ outhi, __nv_bfloat16* __restrict__ outlo,
    int M, int kst, int nc, int act)
{
    extern __shared__ char smem[];
    int tid = threadIdx.x;
    int w = tid >> 5, l = tid & 31;
    int row0 = blockIdx.y * 128, col0 = blockIdx.x * 128;
    int wm = (w & 3) * 32;            // warp row offset
    int wn = (w >> 2) * 64;           // warp col offset
    const __nv_bfloat16* Bh = Bhi + (size_t)col0 * kst;
    const __nv_bfloat16* Bl = Blo + (size_t)col0 * kst;

    float acc[2][8][4];
    #pragma unroll
    for (int mt = 0; mt < 2; mt++)
        #pragma unroll
        for (int nt = 0; nt < 8; nt++)
            #pragma unroll
            for (int q = 0; q < 4; q++) acc[mt][nt][q] = 0.0f;

    uint32_t sbase = smem_to_u32(smem);
    // A ldmatrix.x4: rows wm + mt*16 + (l&15), col half (l>>4)*16  (K=16 chunk)
    uint32_t a_lrow = (uint32_t)(wm + (l & 15));
    uint32_t a_lcol = (uint32_t)((l >> 4) * 16);
    // B ldmatrix.x4 pair covers nt {2pr, 2pr+1}:
    // rows wn + pr*16 + ((l>>4)&1)*8 + (l&7), col half ((l>>3)&1)*16
    uint32_t b_lrow = (uint32_t)(wn + ((l >> 4) & 1) * 8 + (l & 7));
    uint32_t b_lcol = (uint32_t)(((l >> 3) & 1) * 16);

    #pragma unroll
    for (int s = 0; s < NSTAGE - 1; s++) {
        if (s < nc) prefetch_chunk(sbase, s, Ahi, Alo, Bh, Bl, row0, M, kst, s * 16);
        CP_COMMIT();
    }

    for (int c = 0; c < nc; c++) {
        if (c + NSTAGE - 1 < nc)
            prefetch_chunk(sbase, (c + NSTAGE - 1) & (NSTAGE - 1),
                           Ahi, Alo, Bh, Bl, row0, M, kst, (c + NSTAGE - 1) * 16);
        CP_COMMIT();
        CP_WAIT(NSTAGE - 1);
        __syncthreads();
        uint32_t stb = sbase + (c & (NSTAGE - 1)) * STAGE_B;

        uint32_t ah[2][4], al[2][4];
        #pragma unroll
        for (int mt = 0; mt < 2; mt++) {
            uint32_t off = (a_lrow + mt * 16) * SROW + a_lcol;
            LDSM4(ah[mt], stb + off);
            LDSM4(al[mt], stb + TTILE + off);
        }
        #pragma unroll
        for (int pr = 0; pr < 4; pr++) {
            uint32_t off = (b_lrow + pr * 16) * SROW + b_lcol;
            uint32_t bh[4], bl[4];
            LDSM4(bh, stb + 2 * TTILE + off);
            LDSM4(bl, stb + 3 * TTILE + off);
            #pragma unroll
            for (int sub = 0; sub < 2; sub++) {
                int nt = 2 * pr + sub;
                uint32_t* bhf = &bh[2 * sub];
                uint32_t* blf = &bl[2 * sub];
                #pragma unroll
                for (int mt = 0; mt < 2; mt++) {
                    MMA16816(acc[mt][nt], ah[mt], bhf);
                    MMA16816(acc[mt][nt], ah[mt], blf);
                    MMA16816(acc[mt][nt], al[mt], bhf);
                }
            }
        }
        __syncthreads();
    }

    // epilogue: bias + (gelu) + f32 store + optional split-bf16 store
    int gid = l >> 2, tig = l & 3;
    #pragma unroll
    for (int mt = 0; mt < 2; mt++) {
        #pragma unroll
        for (int half = 0; half < 2; half++) {
            int gr = row0 + wm + mt * 16 + gid + half * 8;
            if (gr >= M) continue;
            #pragma unroll
            for (int nt = 0; nt < 8; nt++) {
                int gc = col0 + wn + nt * 8 + 2 * tig;
                float v0 = acc[mt][nt][2 * half + 0] + bias[gc];
                float v1 = acc[mt][nt][2 * half + 1] + bias[gc + 1];
                if (act) { v0 = gelu_f(v0); v1 = gelu_f(v1); }
                size_t ro = (size_t)gr * 256 + gc;
                *reinterpret_cast<float2*>(outf + ro) = make_float2(v0, v1);
                if (outhi) {
                    __nv_bfloat16 h0 = __float2bfloat16(v0);
                    __nv_bfloat16 h1 = __float2bfloat16(v1);
                    __nv_bfloat162 h2; h2.x = h0; h2.y = h1;
                    __nv_bfloat162 l2;
                    l2.x = __float2bfloat16(v0 - __bfloat162float(h0));
                    l2.y = __float2bfloat16(v1 - __bfloat162float(h1));
                    *reinterpret_cast<__nv_bfloat162*>(outhi + ro) = h2;
                    *reinterpret_cast<__nv_bfloat162*>(outlo + ro) = l2;
                }
            }
        }
    }
}

// ---------------- per-layer constants (all layers, data-independent) --------
__global__ void const_all_kernel(
    const float* __restrict__ ln1g, const float* __restrict__ ln1b,
    const float* __restrict__ w1w, const float* __restrict__ w1b)
{
    __shared__ float c0s[4], c1s[4];
    int lyr = blockIdx.x;
    int t = threadIdx.x;
    const float* lg = ln1g + lyr * EDIM;
    const float* lb = ln1b + lyr * EDIM;
    const float* ww = w1w + (size_t)lyr * EDIM * 4;
    if (t < 4) { c0s[t] = 0.0f; c1s[t] = 0.0f; }
    __syncthreads();
    if (t < EDIM) {
        float g = lg[t], bb = lb[t];
        float w0 = ww[t * 4 + 0], w1 = ww[t * 4 + 1];
        float w2 = ww[t * 4 + 2], w3 = ww[t * 4 + 3];
        g_gw4[lyr * EDIM + t] = make_float4(g * w0, g * w1, g * w2, g * w3);
        atomicAdd(&c1s[0], g * w0); atomicAdd(&c1s[1], g * w1);
        atomicAdd(&c1s[2], g * w2); atomicAdd(&c1s[3], g * w3);
        atomicAdd(&c0s[0], bb * w0); atomicAdd(&c0s[1], bb * w1);
        atomicAdd(&c0s[2], bb * w2); atomicAdd(&c0s[3], bb * w3);
    }
    __syncthreads();
    if (t < 4) {
        g_c0[lyr * 4 + t] = c0s[t] + w1b[lyr * 4 + t];
        g_c1[lyr * 4 + t] = c1s[t];
    }
}

// ---------------- per-node stats --------------------------------------------
__global__ void __launch_bounds__(256) node_stats_kernel(const float* __restrict__ xpos, int lyr) {
    int n = (blockIdx.x * blockDim.x + threadIdx.x) >> 5;
    int lane = threadIdx.x & 31;
    if (n >= NN) return;
    const float* mr = g_m + (size_t)n * CC;
    const float4* gw = g_gw4 + lyr * EDIM;
    float s = 0, q = 0;
    float us0 = 0, us1 = 0, us2 = 0, us3 = 0;
    float ud0 = 0, ud1 = 0, ud2 = 0, ud3 = 0;
    #pragma unroll
    for (int j = 0; j < 8; j++) {
        int c = lane + j * 32;
        float v = mr[c];
        s += v; q = fmaf(v, v, q);
        float4 gs = gw[c];
        float4 gd = gw[CC + c];
        us0 = fmaf(v, gs.x, us0); us1 = fmaf(v, gs.y, us1);
        us2 = fmaf(v, gs.z, us2); us3 = fmaf(v, gs.w, us3);
        ud0 = fmaf(v, gd.x, ud0); ud1 = fmaf(v, gd.y, ud1);
        ud2 = fmaf(v, gd.z, ud2); ud3 = fmaf(v, gd.w, ud3);
    }
    if (lane < 3) {
        float p = xpos[n * 3 + lane];
        s += p; q = fmaf(p, p, q);
        float4 gs = gw[2 * CC + lane];
        float4 gd = gw[2 * CC + 3 + lane];
        us0 = fmaf(p, gs.x, us0); us1 = fmaf(p, gs.y, us1);
        us2 = fmaf(p, gs.z, us2); us3 = fmaf(p, gs.w, us3);
        ud0 = fmaf(p, gd.x, ud0); ud1 = fmaf(p, gd.y, ud1);
        ud2 = fmaf(p, gd.z, ud2); ud3 = fmaf(p, gd.w, ud3);
    }
    #pragma unroll
    for (int off = 16; off; off >>= 1) {
        s   += __shfl_xor_sync(0xffffffffu, s, off);
        q   += __shfl_xor_sync(0xffffffffu, q, off);
        us0 += __shfl_xor_sync(0xffffffffu, us0, off);
        us1 += __shfl_xor_sync(0xffffffffu, us1, off);
        us2 += __shfl_xor_sync(0xffffffffu, us2, off);
        us3 += __shfl_xor_sync(0xffffffffu, us3, off);
        ud0 += __shfl_xor_sync(0xffffffffu, ud0, off);
        ud1 += __shfl_xor_sync(0xffffffffu, ud1, off);
        ud2 += __shfl_xor_sync(0xffffffffu, ud2, off);
        ud3 += __shfl_xor_sync(0xffffffffu, ud3, off);
    }
    if (lane == 0) {
        g_S[n] = s; g_Q[n] = q;
        g_us[n] = make_float4(us0, us1, us2, us3);
        g_ud[n] = make_float4(ud0, ud1, ud2, ud3);
    }
}

// ---------------- aggregation ------------------------------------------------
__global__ void __launch_bounds__(256) aggregate_kernel(
    const float* __restrict__ ln2g, const float* __restrict__ ln2b,
    const float* __restrict__ w2w, const float* __restrict__ w2b, int lyr)
{
    int n = blockIdx.x;
    int tid = threadIdx.x;
    __shared__ float ws[128];
    __shared__ int ss[128];
    __shared__ float nc[6];
    const float* c0 = g_c0 + lyr * 4;
    const float* c1 = g_c1 + lyr * 4;
    int beg = g_rowptr[n], end = g_rowptr[n + 1];
    if (tid == 0) {
        nc[0] = g_S[n]; nc[1] = g_Q[n];
        float4 u = g_ud[n];
        nc[2] = u.x; nc[3] = u.y; nc[4] = u.z; nc[5] = u.w;
    }
    __syncthreads();
    float acc = 0.0f;
    for (int e0 = beg; e0 < end; e0 += 128) {
        int cnt = min(128, end - e0);
        if (tid < cnt) {
            int srcn = g_csrc[e0 + tid];
            float4 us = g_us[srcn];
            float mu = (g_S[srcn] + nc[0]) * INV_ED;
            float var = fmaf(-mu, mu, (g_Q[srcn] + nc[1]) * INV_ED);
            float rs = rsqrtf(var + LNEPS);
            float t0 = gelu_f(fmaf(rs, (us.x + nc[2]) - mu * c1[0], c0[0]));
            float t1 = gelu_f(fmaf(rs, (us.y + nc[3]) - mu * c1[1], c0[1]));
            float t2 = gelu_f(fmaf(rs, (us.z + nc[4]) - mu * c1[2], c0[2]));
            float t3 = gelu_f(fmaf(rs, (us.w + nc[5]) - mu * c1[3], c0[3]));
            float mu2 = 0.25f * (t0 + t1 + t2 + t3);
            float d0 = t0 - mu2, d1 = t1 - mu2, d2 = t2 - mu2, d3 = t3 - mu2;
            float var2 = 0.25f * (d0 * d0 + d1 * d1 + d2 * d2 + d3 * d3);
            float rs2 = rsqrtf(var2 + LNEPS);
            float z = (fmaf(d0 * rs2, ln2g[0], ln2b[0])) * w2w[0]
                    + (fmaf(d1 * rs2, ln2g[1], ln2b[1])) * w2w[1]
                    + (fmaf(d2 * rs2, ln2g[2], ln2b[2])) * w2w[2]
                    + (fmaf(d3 * rs2, ln2g[3], ln2b[3])) * w2w[3] + w2b[0];
            ws[tid] = 1.0f / (1.0f + expf(-z));
            ss[tid] = srcn;
        }
        __syncthreads();
        #pragma unroll 4
        for (int i = 0; i < cnt; i++)
            acc = fmaf(g_m[(size_t)ss[i] * CC + tid], ws[i], acc);
        __syncthreads();
    }
    size_t o = (size_t)n * CC + tid;
    __nv_bfloat16 hi = __float2bfloat16(acc);
    g_aghi[o] = hi;
    g_aglo[o] = __float2bfloat16(acc - __bfloat162float(hi));
}

// ---------------- pooling + head --------------------------------------------
__global__ void __launch_bounds__(256) pool_kernel(
    const int* __restrict__ batch, const float* __restrict__ head_w)
{
    int n = (blockIdx.x * blockDim.x + threadIdx.x) >> 5;
    int lane = threadIdx.x & 31;
    if (n >= NN) return;
    const float* hr = g_h + (size_t)n * CC;
    float s = 0;
    #pragma unroll
    for (int j = 0; j < 8; j++)
        s = fmaf(hr[lane + j * 32], head_w[lane + j * 32], s);
    #pragma unroll
    for (int off = 16; off; off >>= 1)
        s += __shfl_xor_sync(0xffffffffu, s, off);
    if (lane == 0) atomicAdd(&g_pool[batch[n]], s);
}
__global__ void final_kernel(float* __restrict__ out, const float* __restrict__ head_b) {
    int g = threadIdx.x;
    if (g < NG)
        out[g] = g_pool[g] / fmaxf((float)g_gcnt[g], 1.0f) + head_b[0];
}

// ---------------- launch -----------------------------------------------------
extern "C" void kernel_launch(void* const* d_in, const int* in_sizes, int n_in,
                              void* d_out, int out_size)
{
    const float* x       = (const float*)d_in[0];
    const float* xpos    = (const float*)d_in[1];
    const int*   ei      = (const int*)  d_in[2];
    const int*   batch   = (const int*)  d_in[3];
    const float* dense_w = (const float*)d_in[4];
    const float* dense_b = (const float*)d_in[5];
    const float* d1_w    = (const float*)d_in[6];
    const float* d1_b    = (const float*)d_in[7];
    const float* ln1_g   = (const float*)d_in[8];
    const float* ln1_b   = (const float*)d_in[9];
    const float* w1_w    = (const float*)d_in[10];
    const float* w1_b    = (const float*)d_in[11];
    const float* ln2_g   = (const float*)d_in[12];
    const float* ln2_b   = (const float*)d_in[13];
    const float* w2_w    = (const float*)d_in[14];
    const float* w2_b    = (const float*)d_in[15];
    const float* d2_w    = (const float*)d_in[16];
    const float* d2_b    = (const float*)d_in[17];
    const float* head_w  = (const float*)d_in[18];
    const float* head_b  = (const float*)d_in[19];

    const int* src = ei;
    const int* dst = ei + NE;

    cudaFuncSetAttribute(gemm_mma_kernel, cudaFuncAttributeMaxDynamicSharedMemorySize, GEMM_SMEM);

    float* p_h;  cudaGetSymbolAddress((void**)&p_h,  g_h);
    float* p_m;  cudaGetSymbolAddress((void**)&p_m,  g_m);
    __nv_bfloat16 *p_xhi, *p_xlo, *p_hhi, *p_hlo, *p_aghi, *p_aglo, *p_wthi, *p_wtlo;
    cudaGetSymbolAddress((void**)&p_xhi, g_xhi);
    cudaGetSymbolAddress((void**)&p_xlo, g_xlo);
    cudaGetSymbolAddress((void**)&p_hhi, g_hhi);
    cudaGetSymbolAddress((void**)&p_hlo, g_hlo);
    cudaGetSymbolAddress((void**)&p_aghi, g_aghi);
    cudaGetSymbolAddress((void**)&p_aglo, g_aglo);
    cudaGetSymbolAddress((void**)&p_wthi, g_wthi);
    cudaGetSymbolAddress((void**)&p_wtlo, g_wtlo);

    dim3 ggrid(2, (NN + 127) / 128);

    // conversions + consts + first GEMMs up front (GEMMs land in ncu window)
    conv_x_kernel<<<(NN * KXP + 255) / 256, 256>>>(x);
    conv_w_kernel<<<(WT_SZ + 255) / 256, 256>>>(dense_w, d1_w, d2_w);
    const_all_kernel<<<NL, 544>>>(ln1_g, ln1_b, w1_w, w1_b);
    gemm_mma_kernel<<<ggrid, 256, GEMM_SMEM>>>(
        p_xhi, p_xlo, p_wthi + WT_DENSE, p_wtlo + WT_DENSE,
        dense_b, p_h, p_hhi, p_hlo, NN, KXP, KXP / 16, 0);
    gemm_mma_kernel<<<ggrid, 256, GEMM_SMEM>>>(
        p_hhi, p_hlo, p_wthi + 256 * KXP, p_wtlo + 256 * KXP,
        d1_b, p_m, nullptr, nullptr, NN, CC, CC / 16, 1);
    node_stats_kernel<<<(NN * 32 + 255) / 256, 256>>>(xpos, 0);

    // CSR build + batch counts (needed before first aggregate)
    zero_kernel<<<(NN + 255) / 256, 256>>>();
    hist2_kernel<<<(NE + 255) / 256, 256>>>(dst, batch);
    scan1_kernel<<<20, 1024>>>();
    scan2_kernel<<<1, 1>>>();
    scan3_kernel<<<(NN + 255) / 256, 256>>>();
    fill_kernel<<<(NE + 255) / 256, 256>>>(src, dst);

    for (int l = 0; l < NL; l++) {
        size_t wd1 = (size_t)256 * KXP + (size_t)(2 * l) * 65536;
        size_t wd2 = (size_t)256 * KXP + (size_t)(2 * l + 1) * 65536;
        if (l > 0) {
            gemm_mma_kernel<<<ggrid, 256, GEMM_SMEM>>>(
                p_hhi, p_hlo, p_wthi + wd1, p_wtlo + wd1,
                d1_b + l * CC, p_m, nullptr, nullptr, NN, CC, CC / 16, 1);
            node_stats_kernel<<<(NN * 32 + 255) / 256, 256>>>(xpos, l);
        }
        aggregate_kernel<<<NN, 256>>>(ln2_g + l * 4, ln2_b + l * 4,
                                      w2_w + l * 4, w2_b + l, l);
        gemm_mma_kernel<<<ggrid, 256, GEMM_SMEM>>>(
            p_aghi, p_aglo, p_wthi + wd2, p_wtlo + wd2,
            d2_b + l * CC, p_h, p_hhi, p_hlo, NN, CC, CC / 16, 1);
    }

    pool_kernel<<<(NN * 32 + 255) / 256, 256>>>(batch, head_w);
    final_kernel<<<1, 32>>>((float*)d_out, head_b);
}

// round 13
// speedup vs baseline: 1.1688x; 1.0513x over previous
#include <cuda_runtime.h>
#include <cuda_bf16.h>
#include <math.h>
#include <stdint.h>

#define NN 20000
#define NE 320000
#define NG 32
#define CC 256
#define NL 4
#define INDIM 739
#define KXP 768            // padded input K (mult of 64)
#define EDIM 518
#define LNEPS 1e-5f
__device__ __constant__ float INV_ED = 1.0f / 518.0f;

// ---------------- scratch (device globals; no allocation allowed) ----------
__device__ float g_h[NN * CC];
__device__ float g_m[NN * CC];
__device__ __nv_bfloat16 g_xhi[NN * KXP];
__device__ __nv_bfloat16 g_xlo[NN * KXP];
__device__ __nv_bfloat16 g_hhi[NN * CC];
__device__ __nv_bfloat16 g_hlo[NN * CC];
__device__ __nv_bfloat16 g_aghi[NN * CC];
__device__ __nv_bfloat16 g_aglo[NN * CC];
// weight table (transposed [N][K], split): dense 256x768, then 8x 256x256
#define WT_DENSE 0
#define WT_SZ (256 * KXP + 8 * 256 * 256)
__device__ __nv_bfloat16 g_wthi[WT_SZ];
__device__ __nv_bfloat16 g_wtlo[WT_SZ];
__device__ float g_S[NN];
__device__ float g_Q[NN];
__device__ float4 g_us[NN];
__device__ float4 g_ud[NN];
__device__ float4 g_gw4[NL * EDIM];
__device__ float g_c0[NL * 4];
__device__ float g_c1[NL * 4];
__device__ int g_cnt[NN];
__device__ int g_rowptr[NN + 1];
__device__ int g_cursor[NN];
__device__ int g_csrc[NE];
__device__ int g_bsum[32];
__device__ float g_pool[NG];
__device__ int g_gcnt[NG];

__device__ __forceinline__ float gelu_f(float x) {
    return 0.5f * x * (1.0f + erff(x * 0.70710678118654752f));
}

__device__ __forceinline__ uint32_t smem_to_u32(const void* p) {
    uint32_t a;
    asm("{ .reg .u64 t; cvta.to.shared.u64 t, %1; cvt.u32.u64 %0, t; }"
        : "=r"(a) : "l"(p));
    return a;
}

#define LDSM4(r, addr) \
    asm volatile("ldmatrix.sync.aligned.m8n8.x4.shared.b16 {%0,%1,%2,%3}, [%4];" \
        : "=r"((r)[0]), "=r"((r)[1]), "=r"((r)[2]), "=r"((r)[3]) : "r"(addr))
#define MMA16816(d, a, b) \
    asm volatile("mma.sync.aligned.m16n8k16.row.col.f32.bf16.bf16.f32 " \
        "{%0,%1,%2,%3}, {%4,%5,%6,%7}, {%8,%9}, {%0,%1,%2,%3};" \
        : "+f"((d)[0]), "+f"((d)[1]), "+f"((d)[2]), "+f"((d)[3]) \
        : "r"((a)[0]), "r"((a)[1]), "r"((a)[2]), "r"((a)[3]), \
          "r"((b)[0]), "r"((b)[1]))
#define CP_ASYNC16(sm, gp) \
    asm volatile("cp.async.cg.shared.global [%0], [%1], 16;" :: "r"(sm), "l"(gp))
#define CP_COMMIT() asm volatile("cp.async.commit_group;" ::: "memory")
#define CP_WAIT(n)  asm volatile("cp.async.wait_group %0;" :: "n"(n) : "memory")

// ---------------- misc small kernels ---------------------------------------
__global__ void zero_kernel() {
    int i = blockIdx.x * blockDim.x + threadIdx.x;
    if (i < NN) g_cnt[i] = 0;
    if (i < NG) { g_gcnt[i] = 0; g_pool[i] = 0.0f; }
}
__global__ void hist2_kernel(const int* __restrict__ dst, const int* __restrict__ batch) {
    int e = blockIdx.x * blockDim.x + threadIdx.x;
    if (e < NE) atomicAdd(&g_cnt[dst[e]], 1);
    if (e < NN) atomicAdd(&g_gcnt[batch[e]], 1);
}
__global__ void scan1_kernel() {
    __shared__ int s[1024];
    int t = threadIdx.x, b = blockIdx.x;
    int i = b * 1024 + t;
    int v = (i < NN) ? g_cnt[i] : 0;
    s[t] = v;
    __syncthreads();
    #pragma unroll
    for (int off = 1; off < 1024; off <<= 1) {
        int x = (t >= off) ? s[t - off] : 0;
        __syncthreads();
        s[t] += x;
        __syncthreads();
    }
    if (i < NN) g_rowptr[i] = s[t] - v;
    if (t == 1023) g_bsum[b] = s[1023];
}
__global__ void scan2_kernel() {
    int run = 0;
    for (int b = 0; b < 20; b++) { int t = g_bsum[b]; g_bsum[b] = run; run += t; }
    g_rowptr[NN] = run;
}
__global__ void scan3_kernel() {
    int i = blockIdx.x * blockDim.x + threadIdx.x;
    if (i < NN) {
        int r = g_rowptr[i] + g_bsum[i >> 10];
        g_rowptr[i] = r;
        g_cursor[i] = r;
    }
}
__global__ void fill_kernel(const int* __restrict__ src, const int* __restrict__ dst) {
    int e = blockIdx.x * blockDim.x + threadIdx.x;
    if (e < NE) {
        int d = dst[e];
        int p = atomicAdd(&g_cursor[d], 1);
        g_csrc[p] = src[e];
    }
}

// ---------------- conversion kernels ----------------------------------------
__global__ void conv_x_kernel(const float* __restrict__ x) {
    int i = blockIdx.x * blockDim.x + threadIdx.x;
    if (i >= NN * KXP) return;
    int n = i / KXP, k = i - n * KXP;
    float v = (k < INDIM) ? x[(size_t)n * INDIM + k] : 0.0f;
    __nv_bfloat16 hi = __float2bfloat16(v);
    g_xhi[i] = hi;
    g_xlo[i] = __float2bfloat16(v - __bfloat162float(hi));
}
__global__ void conv_w_kernel(const float* __restrict__ dense_w,
                              const float* __restrict__ d1_w,
                              const float* __restrict__ d2_w) {
    int i = blockIdx.x * blockDim.x + threadIdx.x;
    if (i >= WT_SZ) return;
    float v;
    if (i < 256 * KXP) {
        int n = i / KXP, k = i - n * KXP;
        v = (k < INDIM) ? dense_w[(size_t)k * 256 + n] : 0.0f;
    } else {
        int j = i - 256 * KXP;
        int mat = j >> 16;            // 0..7
        int r = j & 65535;
        int n = r >> 8, k = r & 255;
        int l = mat >> 1;
        const float* w = (mat & 1) ? d2_w : d1_w;
        v = w[(size_t)l * 65536 + k * 256 + n];
    }
    __nv_bfloat16 hi = __float2bfloat16(v);
    g_wthi[i] = hi;
    g_wtlo[i] = __float2bfloat16(v - __bfloat162float(hi));
}

// ---------------- split-bf16 mma.sync GEMM, cp.async 2-stage -----------------
// C[M,256] = act(A @ B^T + bias); CTA tile 128x128, 8 warps of 32x64,
// K chunks of 32. MMA issue reordered into hh/hl/lh passes over 8
// independent accumulators to break HMMA RAW chains.
#define SROW 80                       // 64B data + 16B pad, conflict-free ldmatrix
#define TTILE (128 * SROW)            // 10240 bytes per (tile,split)
#define STAGE_B (4 * TTILE)           // 40960 bytes per stage
#define GEMM_SMEM (2 * STAGE_B)       // 81920

__device__ __forceinline__ void prefetch_chunk(uint32_t sb, int stage,
        const __nv_bfloat16* __restrict__ Ahi, const __nv_bfloat16* __restrict__ Alo,
        const __nv_bfloat16* __restrict__ Bhi, const __nv_bfloat16* __restrict__ Blo,
        int row0, int M, int kst, int k0) {
    int tid = threadIdx.x;
    uint32_t base = sb + stage * STAGE_B;
    // per tile: 128 rows x 4 granules(16B) = 512 loads / 256 threads = 2 each
    #pragma unroll
    for (int it = 0; it < 2; it++) {
        int g = tid + it * 256;
        int r = g >> 2;
        int gc = g & 3;
        uint32_t soff = (uint32_t)(r * SROW + gc * 16);
        int ra = row0 + r; ra = (ra < M) ? ra : 0;
        size_t aoff = (size_t)ra * kst + k0 + gc * 8;
        CP_ASYNC16(base + soff,             Ahi + aoff);
        CP_ASYNC16(base + TTILE + soff,     Alo + aoff);
        size_t boff = (size_t)r * kst + k0 + gc * 8;   // B rows 0..127 all valid
        CP_ASYNC16(base + 2 * TTILE + soff, Bhi + boff);
        CP_ASYNC16(base + 3 * TTILE + soff, Blo + boff);
    }
}

__global__ void __launch_bounds__(256, 2) gemm_mma_kernel(
    const __nv_bfloat16* __restrict__ Ahi, const __nv_bfloat16* __restrict__ Alo,
    const __nv_bfloat16* __restrict__ Bhi, const __nv_bfloat16* __restrict__ Blo,
    const float* __restrict__ bias, float* __restrict__ outf,
    __nv_bfloat16* __restrict__ outhi, __nv_bfloat16* __restrict__ outlo,
    int M, int kst, int nc, int act)
{
    extern __shared__ char smem[];
    int tid = threadIdx.x;
    int w = tid >> 5, l = tid & 31;
    int row0 = blockIdx.y * 128, col0 = blockIdx.x * 128;
    int wm = (w & 3) * 32;            // warp row offset
    int wn = (w >> 2) * 64;           // warp col offset
    const __nv_bfloat16* Bh = Bhi + (size_t)col0 * kst;
    const __nv_bfloat16* Bl = Blo + (size_t)col0 * kst;

    float acc[2][8][4];
    #pragma unroll
    for (int mt = 0; mt < 2; mt++)
        #pragma unroll
        for (int nt = 0; nt < 8; nt++)
            #pragma unroll
            for (int q = 0; q < 4; q++) acc[mt][nt][q] = 0.0f;

    uint32_t sbase = smem_to_u32(smem);
    // A ldmatrix.x4: rows wm + mt*16 + (l&15), K-half (l>>4)*16
    uint32_t a_lrow = (uint32_t)(wm + (l & 15));
    uint32_t a_lcol = (uint32_t)((l >> 4) * 16);
    // B ldmatrix.x4 pair covers nt {2pr, 2pr+1}:
    // rows wn + pr*16 + ((l>>4)&1)*8 + (l&7), K-half ((l>>3)&1)*16
    uint32_t b_lrow = (uint32_t)(wn + ((l >> 4) & 1) * 8 + (l & 7));
    uint32_t b_lcol = (uint32_t)(((l >> 3) & 1) * 16);

    prefetch_chunk(sbase, 0, Ahi, Alo, Bh, Bl, row0, M, kst, 0);
    CP_COMMIT();

    for (int c = 0; c < nc; c++) {
        if (c + 1 < nc) {
            prefetch_chunk(sbase, (c + 1) & 1, Ahi, Alo, Bh, Bl, row0, M, kst, (c + 1) * 32);
            CP_COMMIT();
            CP_WAIT(1);
        } else {
            CP_WAIT(0);
        }
        __syncthreads();
        uint32_t stb = sbase + (c & 1) * STAGE_B;

        #pragma unroll
        for (int kk = 0; kk < 2; kk++) {
            uint32_t ah[2][4], al[2][4];
            #pragma unroll
            for (int mt = 0; mt < 2; mt++) {
                uint32_t off = (a_lrow + mt * 16) * SROW + kk * 32 + a_lcol;
                LDSM4(ah[mt], stb + off);
                LDSM4(al[mt], stb + TTILE + off);
            }
            #pragma unroll
            for (int prp = 0; prp < 2; prp++) {       // pr pairs {0,1},{2,3}
                uint32_t bh[2][4], bl[2][4];
                #pragma unroll
                for (int q = 0; q < 2; q++) {
                    int pr = 2 * prp + q;
                    uint32_t off = (b_lrow + pr * 16) * SROW + kk * 32 + b_lcol;
                    LDSM4(bh[q], stb + 2 * TTILE + off);
                    LDSM4(bl[q], stb + 3 * TTILE + off);
                }
                // pass 1: hh — 8 independent accumulators
                #pragma unroll
                for (int q = 0; q < 2; q++)
                    #pragma unroll
                    for (int sub = 0; sub < 2; sub++)
                        #pragma unroll
                        for (int mt = 0; mt < 2; mt++)
                            MMA16816(acc[mt][(2 * prp + q) * 2 + sub], ah[mt], &bh[q][2 * sub]);
                // pass 2: hl
                #pragma unroll
                for (int q = 0; q < 2; q++)
                    #pragma unroll
                    for (int sub = 0; sub < 2; sub++)
                        #pragma unroll
                        for (int mt = 0; mt < 2; mt++)
                            MMA16816(acc[mt][(2 * prp + q) * 2 + sub], ah[mt], &bl[q][2 * sub]);
                // pass 3: lh
                #pragma unroll
                for (int q = 0; q < 2; q++)
                    #pragma unroll
                    for (int sub = 0; sub < 2; sub++)
                        #pragma unroll
                        for (int mt = 0; mt < 2; mt++)
                            MMA16816(acc[mt][(2 * prp + q) * 2 + sub], al[mt], &bh[q][2 * sub]);
            }
        }
        __syncthreads();
    }

    // epilogue: bias + (gelu) + f32 store + optional split-bf16 store
    int gid = l >> 2, tig = l & 3;
    #pragma unroll
    for (int mt = 0; mt < 2; mt++) {
        #pragma unroll
        for (int half = 0; half < 2; half++) {
            int gr = row0 + wm + mt * 16 + gid + half * 8;
            if (gr >= M) continue;
            #pragma unroll
            for (int nt = 0; nt < 8; nt++) {
                int gc = col0 + wn + nt * 8 + 2 * tig;
                float v0 = acc[mt][nt][2 * half + 0] + bias[gc];
                float v1 = acc[mt][nt][2 * half + 1] + bias[gc + 1];
                if (act) { v0 = gelu_f(v0); v1 = gelu_f(v1); }
                size_t ro = (size_t)gr * 256 + gc;
                *reinterpret_cast<float2*>(outf + ro) = make_float2(v0, v1);
                if (outhi) {
                    __nv_bfloat16 h0 = __float2bfloat16(v0);
                    __nv_bfloat16 h1 = __float2bfloat16(v1);
                    __nv_bfloat162 h2; h2.x = h0; h2.y = h1;
                    __nv_bfloat162 l2;
                    l2.x = __float2bfloat16(v0 - __bfloat162float(h0));
                    l2.y = __float2bfloat16(v1 - __bfloat162float(h1));
                    *reinterpret_cast<__nv_bfloat162*>(outhi + ro) = h2;
                    *reinterpret_cast<__nv_bfloat162*>(outlo + ro) = l2;
                }
            }
        }
    }
}

// ---------------- per-layer constants (all layers, data-independent) --------
__global__ void const_all_kernel(
    const float* __restrict__ ln1g, const float* __restrict__ ln1b,
    const float* __restrict__ w1w, const float* __restrict__ w1b)
{
    __shared__ float c0s[4], c1s[4];
    int lyr = blockIdx.x;
    int t = threadIdx.x;
    const float* lg = ln1g + lyr * EDIM;
    const float* lb = ln1b + lyr * EDIM;
    const float* ww = w1w + (size_t)lyr * EDIM * 4;
    if (t < 4) { c0s[t] = 0.0f; c1s[t] = 0.0f; }
    __syncthreads();
    if (t < EDIM) {
        float g = lg[t], bb = lb[t];
        float w0 = ww[t * 4 + 0], w1 = ww[t * 4 + 1];
        float w2 = ww[t * 4 + 2], w3 = ww[t * 4 + 3];
        g_gw4[lyr * EDIM + t] = make_float4(g * w0, g * w1, g * w2, g * w3);
        atomicAdd(&c1s[0], g * w0); atomicAdd(&c1s[1], g * w1);
        atomicAdd(&c1s[2], g * w2); atomicAdd(&c1s[3], g * w3);
        atomicAdd(&c0s[0], bb * w0); atomicAdd(&c0s[1], bb * w1);
        atomicAdd(&c0s[2], bb * w2); atomicAdd(&c0s[3], bb * w3);
    }
    __syncthreads();
    if (t < 4) {
        g_c0[lyr * 4 + t] = c0s[t] + w1b[lyr * 4 + t];
        g_c1[lyr * 4 + t] = c1s[t];
    }
}

// ---------------- per-node stats --------------------------------------------
__global__ void __launch_bounds__(256) node_stats_kernel(const float* __restrict__ xpos, int lyr) {
    int n = (blockIdx.x * blockDim.x + threadIdx.x) >> 5;
    int lane = threadIdx.x & 31;
    if (n >= NN) return;
    const float* mr = g_m + (size_t)n * CC;
    const float4* gw = g_gw4 + lyr * EDIM;
    float s = 0, q = 0;
    float us0 = 0, us1 = 0, us2 = 0, us3 = 0;
    float ud0 = 0, ud1 = 0, ud2 = 0, ud3 = 0;
    #pragma unroll
    for (int j = 0; j < 8; j++) {
        int c = lane + j * 32;
        float v = mr[c];
        s += v; q = fmaf(v, v, q);
        float4 gs = gw[c];
        float4 gd = gw[CC + c];
        us0 = fmaf(v, gs.x, us0); us1 = fmaf(v, gs.y, us1);
        us2 = fmaf(v, gs.z, us2); us3 = fmaf(v, gs.w, us3);
        ud0 = fmaf(v, gd.x, ud0); ud1 = fmaf(v, gd.y, ud1);
        ud2 = fmaf(v, gd.z, ud2); ud3 = fmaf(v, gd.w, ud3);
    }
    if (lane < 3) {
        float p = xpos[n * 3 + lane];
        s += p; q = fmaf(p, p, q);
        float4 gs = gw[2 * CC + lane];
        float4 gd = gw[2 * CC + 3 + lane];
        us0 = fmaf(p, gs.x, us0); us1 = fmaf(p, gs.y, us1);
        us2 = fmaf(p, gs.z, us2); us3 = fmaf(p, gs.w, us3);
        ud0 = fmaf(p, gd.x, ud0); ud1 = fmaf(p, gd.y, ud1);
        ud2 = fmaf(p, gd.z, ud2); ud3 = fmaf(p, gd.w, ud3);
    }
    #pragma unroll
    for (int off = 16; off; off >>= 1) {
        s   += __shfl_xor_sync(0xffffffffu, s, off);
        q   += __shfl_xor_sync(0xffffffffu, q, off);
        us0 += __shfl_xor_sync(0xffffffffu, us0, off);
        us1 += __shfl_xor_sync(0xffffffffu, us1, off);
        us2 += __shfl_xor_sync(0xffffffffu, us2, off);
        us3 += __shfl_xor_sync(0xffffffffu, us3, off);
        ud0 += __shfl_xor_sync(0xffffffffu, ud0, off);
        ud1 += __shfl_xor_sync(0xffffffffu, ud1, off);
        ud2 += __shfl_xor_sync(0xffffffffu, ud2, off);
        ud3 += __shfl_xor_sync(0xffffffffu, ud3, off);
    }
    if (lane == 0) {
        g_S[n] = s; g_Q[n] = q;
        g_us[n] = make_float4(us0, us1, us2, us3);
        g_ud[n] = make_float4(ud0, ud1, ud2, ud3);
    }
}

// ---------------- aggregation ------------------------------------------------
__global__ void __launch_bounds__(256) aggregate_kernel(
    const float* __restrict__ ln2g, const float* __restrict__ ln2b,
    const float* __restrict__ w2w, const float* __restrict__ w2b, int lyr)
{
    int n = blockIdx.x;
    int tid = threadIdx.x;
    __shared__ float ws[128];
    __shared__ int ss[128];
    __shared__ float nc[6];
    const float* c0 = g_c0 + lyr * 4;
    const float* c1 = g_c1 + lyr * 4;
    int beg = g_rowptr[n], end = g_rowptr[n + 1];
    if (tid == 0) {
        nc[0] = g_S[n]; nc[1] = g_Q[n];
        float4 u = g_ud[n];
        nc[2] = u.x; nc[3] = u.y; nc[4] = u.z; nc[5] = u.w;
    }
    __syncthreads();
    float acc = 0.0f;
    for (int e0 = beg; e0 < end; e0 += 128) {
        int cnt = min(128, end - e0);
        if (tid < cnt) {
            int srcn = g_csrc[e0 + tid];
            float4 us = g_us[srcn];
            float mu = (g_S[srcn] + nc[0]) * INV_ED;
            float var = fmaf(-mu, mu, (g_Q[srcn] + nc[1]) * INV_ED);
            float rs = rsqrtf(var + LNEPS);
            float t0 = gelu_f(fmaf(rs, (us.x + nc[2]) - mu * c1[0], c0[0]));
            float t1 = gelu_f(fmaf(rs, (us.y + nc[3]) - mu * c1[1], c0[1]));
            float t2 = gelu_f(fmaf(rs, (us.z + nc[4]) - mu * c1[2], c0[2]));
            float t3 = gelu_f(fmaf(rs, (us.w + nc[5]) - mu * c1[3], c0[3]));
            float mu2 = 0.25f * (t0 + t1 + t2 + t3);
            float d0 = t0 - mu2, d1 = t1 - mu2, d2 = t2 - mu2, d3 = t3 - mu2;
            float var2 = 0.25f * (d0 * d0 + d1 * d1 + d2 * d2 + d3 * d3);
            float rs2 = rsqrtf(var2 + LNEPS);
            float z = (fmaf(d0 * rs2, ln2g[0], ln2b[0])) * w2w[0]
                    + (fmaf(d1 * rs2, ln2g[1], ln2b[1])) * w2w[1]
                    + (fmaf(d2 * rs2, ln2g[2], ln2b[2])) * w2w[2]
                    + (fmaf(d3 * rs2, ln2g[3], ln2b[3])) * w2w[3] + w2b[0];
            ws[tid] = 1.0f / (1.0f + expf(-z));
            ss[tid] = srcn;
        }
        __syncthreads();
        #pragma unroll 4
        for (int i = 0; i < cnt; i++)
            acc = fmaf(g_m[(size_t)ss[i] * CC + tid], ws[i], acc);
        __syncthreads();
    }
    size_t o = (size_t)n * CC + tid;
    __nv_bfloat16 hi = __float2bfloat16(acc);
    g_aghi[o] = hi;
    g_aglo[o] = __float2bfloat16(acc - __bfloat162float(hi));
}

// ---------------- pooling + head --------------------------------------------
__global__ void __launch_bounds__(256) pool_kernel(
    const int* __restrict__ batch, const float* __restrict__ head_w)
{
    int n = (blockIdx.x * blockDim.x + threadIdx.x) >> 5;
    int lane = threadIdx.x & 31;
    if (n >= NN) return;
    const float* hr = g_h + (size_t)n * CC;
    float s = 0;
    #pragma unroll
    for (int j = 0; j < 8; j++)
        s = fmaf(hr[lane + j * 32], head_w[lane + j * 32], s);
    #pragma unroll
    for (int off = 16; off; off >>= 1)
        s += __shfl_xor_sync(0xffffffffu, s, off);
    if (lane == 0) atomicAdd(&g_pool[batch[n]], s);
}
__global__ void final_kernel(float* __restrict__ out, const float* __restrict__ head_b) {
    int g = threadIdx.x;
    if (g < NG)
        out[g] = g_pool[g] / fmaxf((float)g_gcnt[g], 1.0f) + head_b[0];
}

// ---------------- launch -----------------------------------------------------
extern "C" void kernel_launch(void* const* d_in, const int* in_sizes, int n_in,
                              void* d_out, int out_size)
{
    const float* x       = (const float*)d_in[0];
    const float* xpos    = (const float*)d_in[1];
    const int*   ei      = (const int*)  d_in[2];
    const int*   batch   = (const int*)  d_in[3];
    const float* dense_w = (const float*)d_in[4];
    const float* dense_b = (const float*)d_in[5];
    const float* d1_w    = (const float*)d_in[6];
    const float* d1_b    = (const float*)d_in[7];
    const float* ln1_g   = (const float*)d_in[8];
    const float* ln1_b   = (const float*)d_in[9];
    const float* w1_w    = (const float*)d_in[10];
    const float* w1_b    = (const float*)d_in[11];
    const float* ln2_g   = (const float*)d_in[12];
    const float* ln2_b   = (const float*)d_in[13];
    const float* w2_w    = (const float*)d_in[14];
    const float* w2_b    = (const float*)d_in[15];
    const float* d2_w    = (const float*)d_in[16];
    const float* d2_b    = (const float*)d_in[17];
    const float* head_w  = (const float*)d_in[18];
    const float* head_b  = (const float*)d_in[19];

    const int* src = ei;
    const int* dst = ei + NE;

    cudaFuncSetAttribute(gemm_mma_kernel, cudaFuncAttributeMaxDynamicSharedMemorySize, GEMM_SMEM);

    float* p_h;  cudaGetSymbolAddress((void**)&p_h,  g_h);
    float* p_m;  cudaGetSymbolAddress((void**)&p_m,  g_m);
    __nv_bfloat16 *p_xhi, *p_xlo, *p_hhi, *p_hlo, *p_aghi, *p_aglo, *p_wthi, *p_wtlo;
    cudaGetSymbolAddress((void**)&p_xhi, g_xhi);
    cudaGetSymbolAddress((void**)&p_xlo, g_xlo);
    cudaGetSymbolAddress((void**)&p_hhi, g_hhi);
    cudaGetSymbolAddress((void**)&p_hlo, g_hlo);
    cudaGetSymbolAddress((void**)&p_aghi, g_aghi);
    cudaGetSymbolAddress((void**)&p_aglo, g_aglo);
    cudaGetSymbolAddress((void**)&p_wthi, g_wthi);
    cudaGetSymbolAddress((void**)&p_wtlo, g_wtlo);

    dim3 ggrid(2, (NN + 127) / 128);

    // conversions + consts + first GEMMs up front (GEMMs land in ncu window)
    conv_x_kernel<<<(NN * KXP + 255) / 256, 256>>>(x);
    conv_w_kernel<<<(WT_SZ + 255) / 256, 256>>>(dense_w, d1_w, d2_w);
    const_all_kernel<<<NL, 544>>>(ln1_g, ln1_b, w1_w, w1_b);
    gemm_mma_kernel<<<ggrid, 256, GEMM_SMEM>>>(
        p_xhi, p_xlo, p_wthi + WT_DENSE, p_wtlo + WT_DENSE,
        dense_b, p_h, p_hhi, p_hlo, NN, KXP, KXP / 32, 0);
    gemm_mma_kernel<<<ggrid, 256, GEMM_SMEM>>>(
        p_hhi, p_hlo, p_wthi + 256 * KXP, p_wtlo + 256 * KXP,
        d1_b, p_m, nullptr, nullptr, NN, CC, CC / 32, 1);
    node_stats_kernel<<<(NN * 32 + 255) / 256, 256>>>(xpos, 0);

    // CSR build + batch counts (needed before first aggregate)
    zero_kernel<<<(NN + 255) / 256, 256>>>();
    hist2_kernel<<<(NE + 255) / 256, 256>>>(dst, batch);
    scan1_kernel<<<20, 1024>>>();
    scan2_kernel<<<1, 1>>>();
    scan3_kernel<<<(NN + 255) / 256, 256>>>();
    fill_kernel<<<(NE + 255) / 256, 256>>>(src, dst);

    for (int l = 0; l < NL; l++) {
        size_t wd1 = (size_t)256 * KXP + (size_t)(2 * l) * 65536;
        size_t wd2 = (size_t)256 * KXP + (size_t)(2 * l + 1) * 65536;
        if (l > 0) {
            gemm_mma_kernel<<<ggrid, 256, GEMM_SMEM>>>(
                p_hhi, p_hlo, p_wthi + wd1, p_wtlo + wd1,
                d1_b + l * CC, p_m, nullptr, nullptr, NN, CC, CC / 32, 1);
            node_stats_kernel<<<(NN * 32 + 255) / 256, 256>>>(xpos, l);
        }
        aggregate_kernel<<<NN, 256>>>(ln2_g + l * 4, ln2_b + l * 4,
                                      w2_w + l * 4, w2_b + l, l);
        gemm_mma_kernel<<<ggrid, 256, GEMM_SMEM>>>(
            p_aghi, p_aglo, p_wthi + wd2, p_wtlo + wd2,
            d2_b + l * CC, p_h, p_hhi, p_hlo, NN, CC, CC / 32, 1);
    }

    pool_kernel<<<(NN * 32 + 255) / 256, 256>>>(batch, head_w);
    final_kernel<<<1, 32>>>((float*)d_out, head_b);
}

// round 15
// speedup vs baseline: 1.1869x; 1.0155x over previous
#include <cuda_runtime.h>
#include <cuda_bf16.h>
#include <math.h>
#include <stdint.h>

#define NN 20000
#define NE 320000
#define NG 32
#define CC 256
#define NL 4
#define INDIM 739
#define KXP 768            // padded input K (mult of 64)
#define EDIM 518
#define LNEPS 1e-5f
__device__ __constant__ float INV_ED = 1.0f / 518.0f;

// ---------------- scratch (device globals; no allocation allowed) ----------
__device__ float g_h[NN * CC];
__device__ float g_m[NN * CC];
__device__ __nv_bfloat16 g_xhi[NN * KXP];
__device__ __nv_bfloat16 g_xlo[NN * KXP];
__device__ __nv_bfloat16 g_hhi[NN * CC];
__device__ __nv_bfloat16 g_hlo[NN * CC];
__device__ __nv_bfloat16 g_aghi[NN * CC];
__device__ __nv_bfloat16 g_aglo[NN * CC];
// weight table (transposed [N][K], split): dense 256x768, then 8x 256x256
#define WT_DENSE 0
#define WT_SZ (256 * KXP + 8 * 256 * 256)
__device__ __nv_bfloat16 g_wthi[WT_SZ];
__device__ __nv_bfloat16 g_wtlo[WT_SZ];
__device__ float g_S[NN];
__device__ float g_Q[NN];
__device__ float4 g_us[NN];
__device__ float4 g_ud[NN];
__device__ float4 g_gw4[NL * EDIM];
__device__ float g_c0[NL * 4];
__device__ float g_c1[NL * 4];
__device__ int g_cnt[NN];
__device__ int g_rowptr[NN + 1];
__device__ int g_cursor[NN];
__device__ int g_csrc[NE];
__device__ int g_bsum[32];
__device__ float g_pool[NG];
__device__ int g_gcnt[NG];

__device__ __forceinline__ float gelu_f(float x) {
    return 0.5f * x * (1.0f + erff(x * 0.70710678118654752f));
}

__device__ __forceinline__ uint32_t smem_to_u32(const void* p) {
    uint32_t a;
    asm("{ .reg .u64 t; cvta.to.shared.u64 t, %1; cvt.u32.u64 %0, t; }"
        : "=r"(a) : "l"(p));
    return a;
}

#define LDSM4(r, addr) \
    asm volatile("ldmatrix.sync.aligned.m8n8.x4.shared.b16 {%0,%1,%2,%3}, [%4];" \
        : "=r"((r)[0]), "=r"((r)[1]), "=r"((r)[2]), "=r"((r)[3]) : "r"(addr))
#define MMA16816(d, a, b) \
    asm volatile("mma.sync.aligned.m16n8k16.row.col.f32.bf16.bf16.f32 " \
        "{%0,%1,%2,%3}, {%4,%5,%6,%7}, {%8,%9}, {%0,%1,%2,%3};" \
        : "+f"((d)[0]), "+f"((d)[1]), "+f"((d)[2]), "+f"((d)[3]) \
        : "r"((a)[0]), "r"((a)[1]), "r"((a)[2]), "r"((a)[3]), \
          "r"((b)[0]), "r"((b)[1]))
#define CP_ASYNC16(sm, gp) \
    asm volatile("cp.async.cg.shared.global [%0], [%1], 16;" :: "r"(sm), "l"(gp))
#define CP_COMMIT() asm volatile("cp.async.commit_group;" ::: "memory")
#define CP_WAIT(n)  asm volatile("cp.async.wait_group %0;" :: "n"(n) : "memory")

// ---------------- misc small kernels ---------------------------------------
__global__ void zero_kernel() {
    int i = blockIdx.x * blockDim.x + threadIdx.x;
    if (i < NN) g_cnt[i] = 0;
    if (i < NG) { g_gcnt[i] = 0; g_pool[i] = 0.0f; }
}
__global__ void hist2_kernel(const int* __restrict__ dst, const int* __restrict__ batch) {
    int e = blockIdx.x * blockDim.x + threadIdx.x;
    if (e < NE) atomicAdd(&g_cnt[dst[e]], 1);
    if (e < NN) atomicAdd(&g_gcnt[batch[e]], 1);
}
__global__ void scan1_kernel() {
    __shared__ int s[1024];
    int t = threadIdx.x, b = blockIdx.x;
    int i = b * 1024 + t;
    int v = (i < NN) ? g_cnt[i] : 0;
    s[t] = v;
    __syncthreads();
    #pragma unroll
    for (int off = 1; off < 1024; off <<= 1) {
        int x = (t >= off) ? s[t - off] : 0;
        __syncthreads();
        s[t] += x;
        __syncthreads();
    }
    if (i < NN) g_rowptr[i] = s[t] - v;
    if (t == 1023) g_bsum[b] = s[1023];
}
__global__ void scan2_kernel() {
    int run = 0;
    for (int b = 0; b < 20; b++) { int t = g_bsum[b]; g_bsum[b] = run; run += t; }
    g_rowptr[NN] = run;
}
__global__ void scan3_kernel() {
    int i = blockIdx.x * blockDim.x + threadIdx.x;
    if (i < NN) {
        int r = g_rowptr[i] + g_bsum[i >> 10];
        g_rowptr[i] = r;
        g_cursor[i] = r;
    }
}
__global__ void fill_kernel(const int* __restrict__ src, const int* __restrict__ dst) {
    int e = blockIdx.x * blockDim.x + threadIdx.x;
    if (e < NE) {
        int d = dst[e];
        int p = atomicAdd(&g_cursor[d], 1);
        g_csrc[p] = src[e];
    }
}

// ---------------- merged conversion kernel ----------------------------------
#define NX (NN * KXP)
__global__ void conv_all_kernel(const float* __restrict__ x,
                                const float* __restrict__ dense_w,
                                const float* __restrict__ d1_w,
                                const float* __restrict__ d2_w) {
    int i = blockIdx.x * blockDim.x + threadIdx.x;
    if (i < NX) {
        int n = i / KXP, k = i - n * KXP;
        float v = (k < INDIM) ? x[(size_t)n * INDIM + k] : 0.0f;
        __nv_bfloat16 hi = __float2bfloat16(v);
        g_xhi[i] = hi;
        g_xlo[i] = __float2bfloat16(v - __bfloat162float(hi));
    } else if (i < NX + WT_SZ) {
        int j = i - NX;
        float v;
        if (j < 256 * KXP) {
            int n = j / KXP, k = j - n * KXP;
            v = (k < INDIM) ? dense_w[(size_t)k * 256 + n] : 0.0f;
        } else {
            int jj = j - 256 * KXP;
            int mat = jj >> 16;
            int r = jj & 65535;
            int n = r >> 8, k = r & 255;
            int lyr = mat >> 1;
            const float* w = (mat & 1) ? d2_w : d1_w;
            v = w[(size_t)lyr * 65536 + k * 256 + n];
        }
        __nv_bfloat16 hi = __float2bfloat16(v);
        g_wthi[j] = hi;
        g_wtlo[j] = __float2bfloat16(v - __bfloat162float(hi));
    }
}

// ---------------- per-layer stats init (xpos terms) --------------------------
__global__ void init_stats_kernel(const float* __restrict__ xpos, int lyr) {
    int n = blockIdx.x * blockDim.x + threadIdx.x;
    if (n >= NN) return;
    const float4* gw = g_gw4 + lyr * EDIM;
    float px = xpos[3 * n], py = xpos[3 * n + 1], pz = xpos[3 * n + 2];
    g_S[n] = px + py + pz;
    g_Q[n] = px * px + py * py + pz * pz;
    float4 a = gw[2 * CC + 0], b = gw[2 * CC + 1], c = gw[2 * CC + 2];
    g_us[n] = make_float4(px * a.x + py * b.x + pz * c.x,
                          px * a.y + py * b.y + pz * c.y,
                          px * a.z + py * b.z + pz * c.z,
                          px * a.w + py * b.w + pz * c.w);
    float4 d = gw[2 * CC + 3], e = gw[2 * CC + 4], f = gw[2 * CC + 5];
    g_ud[n] = make_float4(px * d.x + py * e.x + pz * f.x,
                          px * d.y + py * e.y + pz * f.y,
                          px * d.z + py * e.z + pz * f.z,
                          px * d.w + py * e.w + pz * f.w);
}

// ---------------- split-bf16 mma.sync GEMM, cp.async 2-stage, 1 sync/chunk ---
#define SROW 80                       // 64B data + 16B pad, conflict-free ldmatrix
#define TTILE (128 * SROW)            // 10240 bytes per (tile,split)
#define STAGE_B (4 * TTILE)           // 40960 bytes per stage
#define GEMM_SMEM (2 * STAGE_B)       // 81920

__device__ __forceinline__ void prefetch_chunk(uint32_t sb, int stage,
        const __nv_bfloat16* __restrict__ Ahi, const __nv_bfloat16* __restrict__ Alo,
        const __nv_bfloat16* __restrict__ Bhi, const __nv_bfloat16* __restrict__ Blo,
        int row0, int M, int kst, int k0) {
    int tid = threadIdx.x;
    uint32_t base = sb + stage * STAGE_B;
    #pragma unroll
    for (int it = 0; it < 2; it++) {
        int g = tid + it * 256;
        int r = g >> 2;
        int gc = g & 3;
        uint32_t soff = (uint32_t)(r * SROW + gc * 16);
        int ra = row0 + r; ra = (ra < M) ? ra : 0;
        size_t aoff = (size_t)ra * kst + k0 + gc * 8;
        CP_ASYNC16(base + soff,             Ahi + aoff);
        CP_ASYNC16(base + TTILE + soff,     Alo + aoff);
        size_t boff = (size_t)r * kst + k0 + gc * 8;
        CP_ASYNC16(base + 2 * TTILE + soff, Bhi + boff);
        CP_ASYNC16(base + 3 * TTILE + soff, Blo + boff);
    }
}

__global__ void __launch_bounds__(256, 2) gemm_mma_kernel(
    const __nv_bfloat16* __restrict__ Ahi, const __nv_bfloat16* __restrict__ Alo,
    const __nv_bfloat16* __restrict__ Bhi, const __nv_bfloat16* __restrict__ Blo,
    const float* __restrict__ bias, float* __restrict__ outf,
    __nv_bfloat16* __restrict__ outhi, __nv_bfloat16* __restrict__ outlo,
    int M, int kst, int nc, int act, int lyr, int dostats)
{
    extern __shared__ char smem[];
    int tid = threadIdx.x;
    int w = tid >> 5, l = tid & 31;
    int row0 = blockIdx.y * 128, col0 = blockIdx.x * 128;
    int wm = (w & 3) * 32;
    int wn = (w >> 2) * 64;
    const __nv_bfloat16* Bh = Bhi + (size_t)col0 * kst;
    const __nv_bfloat16* Bl = Blo + (size_t)col0 * kst;

    float acc[2][8][4];
    #pragma unroll
    for (int mt = 0; mt < 2; mt++)
        #pragma unroll
        for (int nt = 0; nt < 8; nt++)
            #pragma unroll
            for (int q = 0; q < 4; q++) acc[mt][nt][q] = 0.0f;

    uint32_t sbase = smem_to_u32(smem);
    uint32_t a_lrow = (uint32_t)(wm + (l & 15));
    uint32_t a_lcol = (uint32_t)((l >> 4) * 16);
    uint32_t b_lrow = (uint32_t)(wn + ((l >> 4) & 1) * 8 + (l & 7));
    uint32_t b_lcol = (uint32_t)(((l >> 3) & 1) * 16);

    prefetch_chunk(sbase, 0, Ahi, Alo, Bh, Bl, row0, M, kst, 0);
    CP_COMMIT();

    for (int c = 0; c < nc; c++) {
        CP_WAIT(0);
        __syncthreads();
        // safe: all warps finished MMA(c-1) (they reached this sync), so the
        // buffer (c+1)&1 — last read during chunk c-1 — can be overwritten.
        if (c + 1 < nc) {
            prefetch_chunk(sbase, (c + 1) & 1, Ahi, Alo, Bh, Bl, row0, M, kst, (c + 1) * 32);
            CP_COMMIT();
        }
        uint32_t stb = sbase + (c & 1) * STAGE_B;

        #pragma unroll
        for (int kk = 0; kk < 2; kk++) {
            uint32_t ah[2][4], al[2][4];
            #pragma unroll
            for (int mt = 0; mt < 2; mt++) {
                uint32_t off = (a_lrow + mt * 16) * SROW + kk * 32 + a_lcol;
                LDSM4(ah[mt], stb + off);
                LDSM4(al[mt], stb + TTILE + off);
            }
            #pragma unroll
            for (int prp = 0; prp < 2; prp++) {
                uint32_t bh[2][4], bl[2][4];
                #pragma unroll
                for (int q = 0; q < 2; q++) {
                    int pr = 2 * prp + q;
                    uint32_t off = (b_lrow + pr * 16) * SROW + kk * 32 + b_lcol;
                    LDSM4(bh[q], stb + 2 * TTILE + off);
                    LDSM4(bl[q], stb + 3 * TTILE + off);
                }
                #pragma unroll
                for (int q = 0; q < 2; q++)
                    #pragma unroll
                    for (int sub = 0; sub < 2; sub++)
                        #pragma unroll
                        for (int mt = 0; mt < 2; mt++)
                            MMA16816(acc[mt][(2 * prp + q) * 2 + sub], ah[mt], &bh[q][2 * sub]);
                #pragma unroll
                for (int q = 0; q < 2; q++)
                    #pragma unroll
                    for (int sub = 0; sub < 2; sub++)
                        #pragma unroll
                        for (int mt = 0; mt < 2; mt++)
                            MMA16816(acc[mt][(2 * prp + q) * 2 + sub], ah[mt], &bl[q][2 * sub]);
                #pragma unroll
                for (int q = 0; q < 2; q++)
                    #pragma unroll
                    for (int sub = 0; sub < 2; sub++)
                        #pragma unroll
                        for (int mt = 0; mt < 2; mt++)
                            MMA16816(acc[mt][(2 * prp + q) * 2 + sub], al[mt], &bh[q][2 * sub]);
            }
        }
    }

    // epilogue: bias + (gelu) + f32 store + optional split-bf16 + fused stats
    int gid = l >> 2, tig = l & 3;
    const float4* gwl = g_gw4 + lyr * EDIM;
    #pragma unroll
    for (int mt = 0; mt < 2; mt++) {
        #pragma unroll
        for (int half = 0; half < 2; half++) {
            int gr = row0 + wm + mt * 16 + gid + half * 8;
            bool rowok = (gr < M);
            float s = 0, q = 0;
            float u0 = 0, u1 = 0, u2 = 0, u3 = 0, u4 = 0, u5 = 0, u6 = 0, u7 = 0;
            #pragma unroll
            for (int nt = 0; nt < 8; nt++) {
                int gc = col0 + wn + nt * 8 + 2 * tig;
                float v0 = acc[mt][nt][2 * half + 0] + bias[gc];
                float v1 = acc[mt][nt][2 * half + 1] + bias[gc + 1];
                if (act) { v0 = gelu_f(v0); v1 = gelu_f(v1); }
                if (rowok) {
                    size_t ro = (size_t)gr * 256 + gc;
                    *reinterpret_cast<float2*>(outf + ro) = make_float2(v0, v1);
                    if (outhi) {
                        __nv_bfloat16 h0 = __float2bfloat16(v0);
                        __nv_bfloat16 h1 = __float2bfloat16(v1);
                        __nv_bfloat162 h2; h2.x = h0; h2.y = h1;
                        __nv_bfloat162 l2;
                        l2.x = __float2bfloat16(v0 - __bfloat162float(h0));
                        l2.y = __float2bfloat16(v1 - __bfloat162float(h1));
                        *reinterpret_cast<__nv_bfloat162*>(outhi + ro) = h2;
                        *reinterpret_cast<__nv_bfloat162*>(outlo + ro) = l2;
                    }
                }
                if (dostats) {
                    s += v0 + v1;
                    q = fmaf(v0, v0, q); q = fmaf(v1, v1, q);
                    float4 gs0 = gwl[gc], gs1 = gwl[gc + 1];
                    float4 gd0 = gwl[CC + gc], gd1 = gwl[CC + gc + 1];
                    u0 = fmaf(v0, gs0.x, fmaf(v1, gs1.x, u0));
                    u1 = fmaf(v0, gs0.y, fmaf(v1, gs1.y, u1));
                    u2 = fmaf(v0, gs0.z, fmaf(v1, gs1.z, u2));
                    u3 = fmaf(v0, gs0.w, fmaf(v1, gs1.w, u3));
                    u4 = fmaf(v0, gd0.x, fmaf(v1, gd1.x, u4));
                    u5 = fmaf(v0, gd0.y, fmaf(v1, gd1.y, u5));
                    u6 = fmaf(v0, gd0.z, fmaf(v1, gd1.z, u6));
                    u7 = fmaf(v0, gd0.w, fmaf(v1, gd1.w, u7));
                }
            }
            if (dostats) {
                #pragma unroll
                for (int d = 1; d <= 2; d <<= 1) {
                    s  += __shfl_xor_sync(0xffffffffu, s,  d);
                    q  += __shfl_xor_sync(0xffffffffu, q,  d);
                    u0 += __shfl_xor_sync(0xffffffffu, u0, d);
                    u1 += __shfl_xor_sync(0xffffffffu, u1, d);
                    u2 += __shfl_xor_sync(0xffffffffu, u2, d);
                    u3 += __shfl_xor_sync(0xffffffffu, u3, d);
                    u4 += __shfl_xor_sync(0xffffffffu, u4, d);
                    u5 += __shfl_xor_sync(0xffffffffu, u5, d);
                    u6 += __shfl_xor_sync(0xffffffffu, u6, d);
                    u7 += __shfl_xor_sync(0xffffffffu, u7, d);
                }
                if (rowok && tig == 0) {
                    atomicAdd(&g_S[gr], s);
                    atomicAdd(&g_Q[gr], q);
                    float* pu = (float*)&g_us[gr];
                    atomicAdd(pu + 0, u0); atomicAdd(pu + 1, u1);
                    atomicAdd(pu + 2, u2); atomicAdd(pu + 3, u3);
                    float* pd = (float*)&g_ud[gr];
                    atomicAdd(pd + 0, u4); atomicAdd(pd + 1, u5);
                    atomicAdd(pd + 2, u6); atomicAdd(pd + 3, u7);
                }
            }
        }
    }
}

// ---------------- per-layer constants (all layers, data-independent) --------
__global__ void const_all_kernel(
    const float* __restrict__ ln1g, const float* __restrict__ ln1b,
    const float* __restrict__ w1w, const float* __restrict__ w1b)
{
    __shared__ float c0s[4], c1s[4];
    int lyr = blockIdx.x;
    int t = threadIdx.x;
    const float* lg = ln1g + lyr * EDIM;
    const float* lb = ln1b + lyr * EDIM;
    const float* ww = w1w + (size_t)lyr * EDIM * 4;
    if (t < 4) { c0s[t] = 0.0f; c1s[t] = 0.0f; }
    __syncthreads();
    if (t < EDIM) {
        float g = lg[t], bb = lb[t];
        float w0 = ww[t * 4 + 0], w1 = ww[t * 4 + 1];
        float w2 = ww[t * 4 + 2], w3 = ww[t * 4 + 3];
        g_gw4[lyr * EDIM + t] = make_float4(g * w0, g * w1, g * w2, g * w3);
        atomicAdd(&c1s[0], g * w0); atomicAdd(&c1s[1], g * w1);
        atomicAdd(&c1s[2], g * w2); atomicAdd(&c1s[3], g * w3);
        atomicAdd(&c0s[0], bb * w0); atomicAdd(&c0s[1], bb * w1);
        atomicAdd(&c0s[2], bb * w2); atomicAdd(&c0s[3], bb * w3);
    }
    __syncthreads();
    if (t < 4) {
        g_c0[lyr * 4 + t] = c0s[t] + w1b[lyr * 4 + t];
        g_c1[lyr * 4 + t] = c1s[t];
    }
}

// ---------------- aggregation ------------------------------------------------
__global__ void __launch_bounds__(256) aggregate_kernel(
    const float* __restrict__ ln2g, const float* __restrict__ ln2b,
    const float* __restrict__ w2w, const float* __restrict__ w2b, int lyr)
{
    int n = blockIdx.x;
    int tid = threadIdx.x;
    __shared__ float ws[128];
    __shared__ int ss[128];
    __shared__ float nc[6];
    const float* c0 = g_c0 + lyr * 4;
    const float* c1 = g_c1 + lyr * 4;
    int beg = g_rowptr[n], end = g_rowptr[n + 1];
    if (tid == 0) {
        nc[0] = g_S[n]; nc[1] = g_Q[n];
        float4 u = g_ud[n];
        nc[2] = u.x; nc[3] = u.y; nc[4] = u.z; nc[5] = u.w;
    }
    __syncthreads();
    float acc = 0.0f;
    for (int e0 = beg; e0 < end; e0 += 128) {
        int cnt = min(128, end - e0);
        if (tid < cnt) {
            int srcn = g_csrc[e0 + tid];
            float4 us = g_us[srcn];
            float mu = (g_S[srcn] + nc[0]) * INV_ED;
            float var = fmaf(-mu, mu, (g_Q[srcn] + nc[1]) * INV_ED);
            float rs = rsqrtf(var + LNEPS);
            float t0 = gelu_f(fmaf(rs, (us.x + nc[2]) - mu * c1[0], c0[0]));
            float t1 = gelu_f(fmaf(rs, (us.y + nc[3]) - mu * c1[1], c0[1]));
            float t2 = gelu_f(fmaf(rs, (us.z + nc[4]) - mu * c1[2], c0[2]));
            float t3 = gelu_f(fmaf(rs, (us.w + nc[5]) - mu * c1[3], c0[3]));
            float mu2 = 0.25f * (t0 + t1 + t2 + t3);
            float d0 = t0 - mu2, d1 = t1 - mu2, d2 = t2 - mu2, d3 = t3 - mu2;
            float var2 = 0.25f * (d0 * d0 + d1 * d1 + d2 * d2 + d3 * d3);
            float rs2 = rsqrtf(var2 + LNEPS);
            float z = (fmaf(d0 * rs2, ln2g[0], ln2b[0])) * w2w[0]
                    + (fmaf(d1 * rs2, ln2g[1], ln2b[1])) * w2w[1]
                    + (fmaf(d2 * rs2, ln2g[2], ln2b[2])) * w2w[2]
                    + (fmaf(d3 * rs2, ln2g[3], ln2b[3])) * w2w[3] + w2b[0];
            ws[tid] = 1.0f / (1.0f + expf(-z));
            ss[tid] = srcn;
        }
        __syncthreads();
        #pragma unroll 4
        for (int i = 0; i < cnt; i++)
            acc = fmaf(g_m[(size_t)ss[i] * CC + tid], ws[i], acc);
        __syncthreads();
    }
    size_t o = (size_t)n * CC + tid;
    __nv_bfloat16 hi = __float2bfloat16(acc);
    g_aghi[o] = hi;
    g_aglo[o] = __float2bfloat16(acc - __bfloat162float(hi));
}

// ---------------- pooling + head --------------------------------------------
__global__ void __launch_bounds__(256) pool_kernel(
    const int* __restrict__ batch, const float* __restrict__ head_w)
{
    int n = (blockIdx.x * blockDim.x + threadIdx.x) >> 5;
    int lane = threadIdx.x & 31;
    if (n >= NN) return;
    const float* hr = g_h + (size_t)n * CC;
    float s = 0;
    #pragma unroll
    for (int j = 0; j < 8; j++)
        s = fmaf(hr[lane + j * 32], head_w[lane + j * 32], s);
    #pragma unroll
    for (int off = 16; off; off >>= 1)
        s += __shfl_xor_sync(0xffffffffu, s, off);
    if (lane == 0) atomicAdd(&g_pool[batch[n]], s);
}
__global__ void final_kernel(float* __restrict__ out, const float* __restrict__ head_b) {
    int g = threadIdx.x;
    if (g < NG)
        out[g] = g_pool[g] / fmaxf((float)g_gcnt[g], 1.0f) + head_b[0];
}

// ---------------- launch -----------------------------------------------------
extern "C" void kernel_launch(void* const* d_in, const int* in_sizes, int n_in,
                              void* d_out, int out_size)
{
    const float* x       = (const float*)d_in[0];
    const float* xpos    = (const float*)d_in[1];
    const int*   ei      = (const int*)  d_in[2];
    const int*   batch   = (const int*)  d_in[3];
    const float* dense_w = (const float*)d_in[4];
    const float* dense_b = (const float*)d_in[5];
    const float* d1_w    = (const float*)d_in[6];
    const float* d1_b    = (const float*)d_in[7];
    const float* ln1_g   = (const float*)d_in[8];
    const float* ln1_b   = (const float*)d_in[9];
    const float* w1_w    = (const float*)d_in[10];
    const float* w1_b    = (const float*)d_in[11];
    const float* ln2_g   = (const float*)d_in[12];
    const float* ln2_b   = (const float*)d_in[13];
    const float* w2_w    = (const float*)d_in[14];
    const float* w2_b    = (const float*)d_in[15];
    const float* d2_w    = (const float*)d_in[16];
    const float* d2_b    = (const float*)d_in[17];
    const float* head_w  = (const float*)d_in[18];
    const float* head_b  = (const float*)d_in[19];

    const int* src = ei;
    const int* dst = ei + NE;

    cudaFuncSetAttribute(gemm_mma_kernel, cudaFuncAttributeMaxDynamicSharedMemorySize, GEMM_SMEM);

    float* p_h;  cudaGetSymbolAddress((void**)&p_h,  g_h);
    float* p_m;  cudaGetSymbolAddress((void**)&p_m,  g_m);
    __nv_bfloat16 *p_xhi, *p_xlo, *p_hhi, *p_hlo, *p_aghi, *p_aglo, *p_wthi, *p_wtlo;
    cudaGetSymbolAddress((void**)&p_xhi, g_xhi);
    cudaGetSymbolAddress((void**)&p_xlo, g_xlo);
    cudaGetSymbolAddress((void**)&p_hhi, g_hhi);
    cudaGetSymbolAddress((void**)&p_hlo, g_hlo);
    cudaGetSymbolAddress((void**)&p_aghi, g_aghi);
    cudaGetSymbolAddress((void**)&p_aglo, g_aglo);
    cudaGetSymbolAddress((void**)&p_wthi, g_wthi);
    cudaGetSymbolAddress((void**)&p_wtlo, g_wtlo);

    dim3 ggrid(2, (NN + 127) / 128);

    conv_all_kernel<<<(NX + WT_SZ + 255) / 256, 256>>>(x, dense_w, d1_w, d2_w);
    const_all_kernel<<<NL, 544>>>(ln1_g, ln1_b, w1_w, w1_b);
    init_stats_kernel<<<(NN + 255) / 256, 256>>>(xpos, 0);
    // h = x @ dense_w + b (no act, split out, no stats)
    gemm_mma_kernel<<<ggrid, 256, GEMM_SMEM>>>(
        p_xhi, p_xlo, p_wthi + WT_DENSE, p_wtlo + WT_DENSE,
        dense_b, p_h, p_hhi, p_hlo, NN, KXP, KXP / 32, 0, 0, 0);
    // m = gelu(h @ d1_w + b), stats fused (layer 0)
    gemm_mma_kernel<<<ggrid, 256, GEMM_SMEM>>>(
        p_hhi, p_hlo, p_wthi + 256 * KXP, p_wtlo + 256 * KXP,
        d1_b, p_m, nullptr, nullptr, NN, CC, CC / 32, 1, 0, 1);

    // CSR build + batch counts (needed before first aggregate)
    zero_kernel<<<(NN + 255) / 256, 256>>>();
    hist2_kernel<<<(NE + 255) / 256, 256>>>(dst, batch);
    scan1_kernel<<<20, 1024>>>();
    scan2_kernel<<<1, 1>>>();
    scan3_kernel<<<(NN + 255) / 256, 256>>>();
    fill_kernel<<<(NE + 255) / 256, 256>>>(src, dst);

    for (int l = 0; l < NL; l++) {
        size_t wd1 = (size_t)256 * KXP + (size_t)(2 * l) * 65536;
        size_t wd2 = (size_t)256 * KXP + (size_t)(2 * l + 1) * 65536;
        if (l > 0) {
            gemm_mma_kernel<<<ggrid, 256, GEMM_SMEM>>>(
                p_hhi, p_hlo, p_wthi + wd1, p_wtlo + wd1,
                d1_b + l * CC, p_m, nullptr, nullptr, NN, CC, CC / 32, 1, l, 1);
        }
        aggregate_kernel<<<NN, 256>>>(ln2_g + l * 4, ln2_b + l * 4,
                                      w2_w + l * 4, w2_b + l, l);
        if (l + 1 < NL)
            init_stats_kernel<<<(NN + 255) / 256, 256>>>(xpos, l + 1);
        gemm_mma_kernel<<<ggrid, 256, GEMM_SMEM>>>(
            p_aghi, p_aglo, p_wthi + wd2, p_wtlo + wd2,
            d2_b + l * CC, p_h, p_hhi, p_hlo, NN, CC, CC / 32, 1, 0, 0);
    }

    pool_kernel<<<(NN * 32 + 255) / 256, 256>>>(batch, head_w);
    final_kernel<<<1, 32>>>((float*)d_out, head_b);
}

// round 16
// speedup vs baseline: 1.2615x; 1.0628x over previous
#include <cuda_runtime.h>
#include <cuda_bf16.h>
#include <math.h>
#include <stdint.h>

#define NN 20000
#define NE 320000
#define NG 32
#define CC 256
#define NL 4
#define INDIM 739
#define KXP 768            // padded input K (mult of 64)
#define EDIM 518
#define LNEPS 1e-5f
__device__ __constant__ float INV_ED = 1.0f / 518.0f;

// ---------------- scratch (device globals; no allocation allowed) ----------
__device__ float g_h[NN * CC];
__device__ float g_m[NN * CC];
__device__ __nv_bfloat16 g_xhi[NN * KXP];
__device__ __nv_bfloat16 g_xlo[NN * KXP];
__device__ __nv_bfloat16 g_hhi[NN * CC];
__device__ __nv_bfloat16 g_hlo[NN * CC];
__device__ __nv_bfloat16 g_aghi[NN * CC];
__device__ __nv_bfloat16 g_aglo[NN * CC];
// weight table (transposed [N][K], split): dense 256x768, then 8x 256x256
#define WT_DENSE 0
#define WT_SZ (256 * KXP + 8 * 256 * 256)
__device__ __nv_bfloat16 g_wthi[WT_SZ];
__device__ __nv_bfloat16 g_wtlo[WT_SZ];
__device__ float g_S[NN];
__device__ float g_Q[NN];
__device__ float4 g_us[NN];
__device__ float4 g_ud[NN];
__device__ float4 g_gw4[NL * EDIM];
__device__ float g_c0[NL * 4];
__device__ float g_c1[NL * 4];
__device__ int g_cnt[NN];
__device__ int g_rowptr[NN + 1];
__device__ int g_cursor[NN];
__device__ int g_csrc[NE];
__device__ int g_bsum[32];
__device__ float g_pool[NG];
__device__ int g_gcnt[NG];

__device__ __forceinline__ float gelu_f(float x) {
    return 0.5f * x * (1.0f + erff(x * 0.70710678118654752f));
}

__device__ __forceinline__ uint32_t smem_to_u32(const void* p) {
    uint32_t a;
    asm("{ .reg .u64 t; cvta.to.shared.u64 t, %1; cvt.u32.u64 %0, t; }"
        : "=r"(a) : "l"(p));
    return a;
}

#define LDSM4(r, addr) \
    asm volatile("ldmatrix.sync.aligned.m8n8.x4.shared.b16 {%0,%1,%2,%3}, [%4];" \
        : "=r"((r)[0]), "=r"((r)[1]), "=r"((r)[2]), "=r"((r)[3]) : "r"(addr))
#define MMA16816(d, a, b) \
    asm volatile("mma.sync.aligned.m16n8k16.row.col.f32.bf16.bf16.f32 " \
        "{%0,%1,%2,%3}, {%4,%5,%6,%7}, {%8,%9}, {%0,%1,%2,%3};" \
        : "+f"((d)[0]), "+f"((d)[1]), "+f"((d)[2]), "+f"((d)[3]) \
        : "r"((a)[0]), "r"((a)[1]), "r"((a)[2]), "r"((a)[3]), \
          "r"((b)[0]), "r"((b)[1]))
#define CP_ASYNC16(sm, gp) \
    asm volatile("cp.async.cg.shared.global [%0], [%1], 16;" :: "r"(sm), "l"(gp))
#define CP_COMMIT() asm volatile("cp.async.commit_group;" ::: "memory")
#define CP_WAIT(n)  asm volatile("cp.async.wait_group %0;" :: "n"(n) : "memory")

// ---------------- misc small kernels ---------------------------------------
__global__ void zero_kernel() {
    int i = blockIdx.x * blockDim.x + threadIdx.x;
    if (i < NN) g_cnt[i] = 0;
    if (i < NG) { g_gcnt[i] = 0; g_pool[i] = 0.0f; }
}
__global__ void hist2_kernel(const int* __restrict__ dst, const int* __restrict__ batch) {
    int e = blockIdx.x * blockDim.x + threadIdx.x;
    if (e < NE) atomicAdd(&g_cnt[dst[e]], 1);
    if (e < NN) atomicAdd(&g_gcnt[batch[e]], 1);
}
__global__ void scan1_kernel() {
    __shared__ int s[1024];
    int t = threadIdx.x, b = blockIdx.x;
    int i = b * 1024 + t;
    int v = (i < NN) ? g_cnt[i] : 0;
    s[t] = v;
    __syncthreads();
    #pragma unroll
    for (int off = 1; off < 1024; off <<= 1) {
        int x = (t >= off) ? s[t - off] : 0;
        __syncthreads();
        s[t] += x;
        __syncthreads();
    }
    if (i < NN) g_rowptr[i] = s[t] - v;
    if (t == 1023) g_bsum[b] = s[1023];
}
__global__ void scan2_kernel() {
    int run = 0;
    for (int b = 0; b < 20; b++) { int t = g_bsum[b]; g_bsum[b] = run; run += t; }
    g_rowptr[NN] = run;
}
__global__ void scan3_kernel() {
    int i = blockIdx.x * blockDim.x + threadIdx.x;
    if (i < NN) {
        int r = g_rowptr[i] + g_bsum[i >> 10];
        g_rowptr[i] = r;
        g_cursor[i] = r;
    }
}
__global__ void fill_kernel(const int* __restrict__ src, const int* __restrict__ dst) {
    int e = blockIdx.x * blockDim.x + threadIdx.x;
    if (e < NE) {
        int d = dst[e];
        int p = atomicAdd(&g_cursor[d], 1);
        g_csrc[p] = src[e];
    }
}

// ---------------- merged conversion kernel ----------------------------------
#define NX (NN * KXP)
__global__ void conv_all_kernel(const float* __restrict__ x,
                                const float* __restrict__ dense_w,
                                const float* __restrict__ d1_w,
                                const float* __restrict__ d2_w) {
    int i = blockIdx.x * blockDim.x + threadIdx.x;
    if (i < NX) {
        int n = i / KXP, k = i - n * KXP;
        float v = (k < INDIM) ? x[(size_t)n * INDIM + k] : 0.0f;
        __nv_bfloat16 hi = __float2bfloat16(v);
        g_xhi[i] = hi;
        g_xlo[i] = __float2bfloat16(v - __bfloat162float(hi));
    } else if (i < NX + WT_SZ) {
        int j = i - NX;
        float v;
        if (j < 256 * KXP) {
            int n = j / KXP, k = j - n * KXP;
            v = (k < INDIM) ? dense_w[(size_t)k * 256 + n] : 0.0f;
        } else {
            int jj = j - 256 * KXP;
            int mat = jj >> 16;
            int r = jj & 65535;
            int n = r >> 8, k = r & 255;
            int lyr = mat >> 1;
            const float* w = (mat & 1) ? d2_w : d1_w;
            v = w[(size_t)lyr * 65536 + k * 256 + n];
        }
        __nv_bfloat16 hi = __float2bfloat16(v);
        g_wthi[j] = hi;
        g_wtlo[j] = __float2bfloat16(v - __bfloat162float(hi));
    }
}

// ---------------- per-layer stats init (xpos terms) --------------------------
__global__ void init_stats_kernel(const float* __restrict__ xpos, int lyr) {
    int n = blockIdx.x * blockDim.x + threadIdx.x;
    if (n >= NN) return;
    const float4* gw = g_gw4 + lyr * EDIM;
    float px = xpos[3 * n], py = xpos[3 * n + 1], pz = xpos[3 * n + 2];
    g_S[n] = px + py + pz;
    g_Q[n] = px * px + py * py + pz * pz;
    float4 a = gw[2 * CC + 0], b = gw[2 * CC + 1], c = gw[2 * CC + 2];
    g_us[n] = make_float4(px * a.x + py * b.x + pz * c.x,
                          px * a.y + py * b.y + pz * c.y,
                          px * a.z + py * b.z + pz * c.z,
                          px * a.w + py * b.w + pz * c.w);
    float4 d = gw[2 * CC + 3], e = gw[2 * CC + 4], f = gw[2 * CC + 5];
    g_ud[n] = make_float4(px * d.x + py * e.x + pz * f.x,
                          px * d.y + py * e.y + pz * f.y,
                          px * d.z + py * e.z + pz * f.z,
                          px * d.w + py * e.w + pz * f.w);
}

// ---------------- split-bf16 mma.sync GEMM ----------------------------------
// CTA tile 128x64, 8 warps of 32x32, chunk 32, 2-stage cp.async, 3 CTAs/SM.
#define SROW 80                       // 64B data + 16B pad, conflict-free ldmatrix
#define ATILE (128 * SROW)            // 10240
#define BTILE (64 * SROW)             // 5120
#define STAGE_B (2 * ATILE + 2 * BTILE)   // 30720
#define GEMM_SMEM (2 * STAGE_B)           // 61440

__device__ __forceinline__ void prefetch_chunk(uint32_t sb, int stage,
        const __nv_bfloat16* __restrict__ Ahi, const __nv_bfloat16* __restrict__ Alo,
        const __nv_bfloat16* __restrict__ Bh, const __nv_bfloat16* __restrict__ Bl,
        int row0, int M, int kst, int k0) {
    int tid = threadIdx.x;
    uint32_t base = sb + stage * STAGE_B;
    // A: 128 rows x 4 granules = 512 slots, 2 per thread
    #pragma unroll
    for (int it = 0; it < 2; it++) {
        int g = tid + it * 256;
        int r = g >> 2;
        int gc = g & 3;
        uint32_t soff = (uint32_t)(r * SROW + gc * 16);
        int ra = row0 + r; ra = (ra < M) ? ra : 0;
        size_t aoff = (size_t)ra * kst + k0 + gc * 8;
        CP_ASYNC16(base + soff,         Ahi + aoff);
        CP_ASYNC16(base + ATILE + soff, Alo + aoff);
    }
    // B: 64 rows x 4 granules = 256 slots, 1 per thread
    {
        int r = tid >> 2;
        int gc = tid & 3;
        uint32_t soff = (uint32_t)(r * SROW + gc * 16);
        size_t boff = (size_t)r * kst + k0 + gc * 8;
        CP_ASYNC16(base + 2 * ATILE + soff,         Bh + boff);
        CP_ASYNC16(base + 2 * ATILE + BTILE + soff, Bl + boff);
    }
}

__global__ void __launch_bounds__(256, 3) gemm_mma_kernel(
    const __nv_bfloat16* __restrict__ Ahi, const __nv_bfloat16* __restrict__ Alo,
    const __nv_bfloat16* __restrict__ Bhi, const __nv_bfloat16* __restrict__ Blo,
    const float* __restrict__ bias, float* __restrict__ outf,
    __nv_bfloat16* __restrict__ outhi, __nv_bfloat16* __restrict__ outlo,
    int M, int kst, int nc, int act, int lyr, int dostats)
{
    extern __shared__ char smem[];
    int tid = threadIdx.x;
    int w = tid >> 5, l = tid & 31;
    int row0 = blockIdx.y * 128, col0 = blockIdx.x * 64;
    int wm = (w & 3) * 32;            // 4 row positions
    int wn = (w >> 2) * 32;           // 2 col positions
    const __nv_bfloat16* Bh = Bhi + (size_t)col0 * kst;
    const __nv_bfloat16* Bl = Blo + (size_t)col0 * kst;

    float acc[2][4][4];
    #pragma unroll
    for (int mt = 0; mt < 2; mt++)
        #pragma unroll
        for (int nt = 0; nt < 4; nt++)
            #pragma unroll
            for (int q = 0; q < 4; q++) acc[mt][nt][q] = 0.0f;

    uint32_t sbase = smem_to_u32(smem);
    uint32_t a_lrow = (uint32_t)(wm + (l & 15));
    uint32_t a_lcol = (uint32_t)((l >> 4) * 16);
    uint32_t b_lrow = (uint32_t)(wn + ((l >> 4) & 1) * 8 + (l & 7));
    uint32_t b_lcol = (uint32_t)(((l >> 3) & 1) * 16);

    prefetch_chunk(sbase, 0, Ahi, Alo, Bh, Bl, row0, M, kst, 0);
    CP_COMMIT();

    for (int c = 0; c < nc; c++) {
        CP_WAIT(0);
        __syncthreads();
        if (c + 1 < nc) {
            prefetch_chunk(sbase, (c + 1) & 1, Ahi, Alo, Bh, Bl, row0, M, kst, (c + 1) * 32);
            CP_COMMIT();
        }
        uint32_t stb = sbase + (c & 1) * STAGE_B;

        #pragma unroll
        for (int kk = 0; kk < 2; kk++) {
            uint32_t ah[2][4], al[2][4], bh[2][4], bl[2][4];
            #pragma unroll
            for (int mt = 0; mt < 2; mt++) {
                uint32_t off = (a_lrow + mt * 16) * SROW + kk * 32 + a_lcol;
                LDSM4(ah[mt], stb + off);
                LDSM4(al[mt], stb + ATILE + off);
            }
            #pragma unroll
            for (int pr = 0; pr < 2; pr++) {
                uint32_t off = (b_lrow + pr * 16) * SROW + kk * 32 + b_lcol;
                LDSM4(bh[pr], stb + 2 * ATILE + off);
                LDSM4(bl[pr], stb + 2 * ATILE + BTILE + off);
            }
            // pass hh: 8 independent accumulators
            #pragma unroll
            for (int pr = 0; pr < 2; pr++)
                #pragma unroll
                for (int sub = 0; sub < 2; sub++)
                    #pragma unroll
                    for (int mt = 0; mt < 2; mt++)
                        MMA16816(acc[mt][pr * 2 + sub], ah[mt], &bh[pr][2 * sub]);
            // pass hl
            #pragma unroll
            for (int pr = 0; pr < 2; pr++)
                #pragma unroll
                for (int sub = 0; sub < 2; sub++)
                    #pragma unroll
                    for (int mt = 0; mt < 2; mt++)
                        MMA16816(acc[mt][pr * 2 + sub], ah[mt], &bl[pr][2 * sub]);
            // pass lh
            #pragma unroll
            for (int pr = 0; pr < 2; pr++)
                #pragma unroll
                for (int sub = 0; sub < 2; sub++)
                    #pragma unroll
                    for (int mt = 0; mt < 2; mt++)
                        MMA16816(acc[mt][pr * 2 + sub], al[mt], &bh[pr][2 * sub]);
        }
    }

    // epilogue: bias + (gelu) + f32 store + optional split-bf16 + fused stats
    int gid = l >> 2, tig = l & 3;
    const float4* gwl = g_gw4 + lyr * EDIM;
    #pragma unroll
    for (int mt = 0; mt < 2; mt++) {
        #pragma unroll
        for (int half = 0; half < 2; half++) {
            int gr = row0 + wm + mt * 16 + gid + half * 8;
            bool rowok = (gr < M);
            float s = 0, q = 0;
            float u0 = 0, u1 = 0, u2 = 0, u3 = 0, u4 = 0, u5 = 0, u6 = 0, u7 = 0;
            #pragma unroll
            for (int nt = 0; nt < 4; nt++) {
                int gc = col0 + wn + nt * 8 + 2 * tig;
                float v0 = acc[mt][nt][2 * half + 0] + bias[gc];
                float v1 = acc[mt][nt][2 * half + 1] + bias[gc + 1];
                if (act) { v0 = gelu_f(v0); v1 = gelu_f(v1); }
                if (rowok) {
                    size_t ro = (size_t)gr * 256 + gc;
                    *reinterpret_cast<float2*>(outf + ro) = make_float2(v0, v1);
                    if (outhi) {
                        __nv_bfloat16 h0 = __float2bfloat16(v0);
                        __nv_bfloat16 h1 = __float2bfloat16(v1);
                        __nv_bfloat162 h2; h2.x = h0; h2.y = h1;
                        __nv_bfloat162 l2;
                        l2.x = __float2bfloat16(v0 - __bfloat162float(h0));
                        l2.y = __float2bfloat16(v1 - __bfloat162float(h1));
                        *reinterpret_cast<__nv_bfloat162*>(outhi + ro) = h2;
                        *reinterpret_cast<__nv_bfloat162*>(outlo + ro) = l2;
                    }
                }
                if (dostats) {
                    s += v0 + v1;
                    q = fmaf(v0, v0, q); q = fmaf(v1, v1, q);
                    float4 gs0 = gwl[gc], gs1 = gwl[gc + 1];
                    float4 gd0 = gwl[CC + gc], gd1 = gwl[CC + gc + 1];
                    u0 = fmaf(v0, gs0.x, fmaf(v1, gs1.x, u0));
                    u1 = fmaf(v0, gs0.y, fmaf(v1, gs1.y, u1));
                    u2 = fmaf(v0, gs0.z, fmaf(v1, gs1.z, u2));
                    u3 = fmaf(v0, gs0.w, fmaf(v1, gs1.w, u3));
                    u4 = fmaf(v0, gd0.x, fmaf(v1, gd1.x, u4));
                    u5 = fmaf(v0, gd0.y, fmaf(v1, gd1.y, u5));
                    u6 = fmaf(v0, gd0.z, fmaf(v1, gd1.z, u6));
                    u7 = fmaf(v0, gd0.w, fmaf(v1, gd1.w, u7));
                }
            }
            if (dostats) {
                #pragma unroll
                for (int d = 1; d <= 2; d <<= 1) {
                    s  += __shfl_xor_sync(0xffffffffu, s,  d);
                    q  += __shfl_xor_sync(0xffffffffu, q,  d);
                    u0 += __shfl_xor_sync(0xffffffffu, u0, d);
                    u1 += __shfl_xor_sync(0xffffffffu, u1, d);
                    u2 += __shfl_xor_sync(0xffffffffu, u2, d);
                    u3 += __shfl_xor_sync(0xffffffffu, u3, d);
                    u4 += __shfl_xor_sync(0xffffffffu, u4, d);
                    u5 += __shfl_xor_sync(0xffffffffu, u5, d);
                    u6 += __shfl_xor_sync(0xffffffffu, u6, d);
                    u7 += __shfl_xor_sync(0xffffffffu, u7, d);
                }
                if (rowok && tig == 0) {
                    atomicAdd(&g_S[gr], s);
                    atomicAdd(&g_Q[gr], q);
                    float* pu = (float*)&g_us[gr];
                    atomicAdd(pu + 0, u0); atomicAdd(pu + 1, u1);
                    atomicAdd(pu + 2, u2); atomicAdd(pu + 3, u3);
                    float* pd = (float*)&g_ud[gr];
                    atomicAdd(pd + 0, u4); atomicAdd(pd + 1, u5);
                    atomicAdd(pd + 2, u6); atomicAdd(pd + 3, u7);
                }
            }
        }
    }
}

// ---------------- per-layer constants (all layers, data-independent) --------
__global__ void const_all_kernel(
    const float* __restrict__ ln1g, const float* __restrict__ ln1b,
    const float* __restrict__ w1w, const float* __restrict__ w1b)
{
    __shared__ float c0s[4], c1s[4];
    int lyr = blockIdx.x;
    int t = threadIdx.x;
    const float* lg = ln1g + lyr * EDIM;
    const float* lb = ln1b + lyr * EDIM;
    const float* ww = w1w + (size_t)lyr * EDIM * 4;
    if (t < 4) { c0s[t] = 0.0f; c1s[t] = 0.0f; }
    __syncthreads();
    if (t < EDIM) {
        float g = lg[t], bb = lb[t];
        float w0 = ww[t * 4 + 0], w1 = ww[t * 4 + 1];
        float w2 = ww[t * 4 + 2], w3 = ww[t * 4 + 3];
        g_gw4[lyr * EDIM + t] = make_float4(g * w0, g * w1, g * w2, g * w3);
        atomicAdd(&c1s[0], g * w0); atomicAdd(&c1s[1], g * w1);
        atomicAdd(&c1s[2], g * w2); atomicAdd(&c1s[3], g * w3);
        atomicAdd(&c0s[0], bb * w0); atomicAdd(&c0s[1], bb * w1);
        atomicAdd(&c0s[2], bb * w2); atomicAdd(&c0s[3], bb * w3);
    }
    __syncthreads();
    if (t < 4) {
        g_c0[lyr * 4 + t] = c0s[t] + w1b[lyr * 4 + t];
        g_c1[lyr * 4 + t] = c1s[t];
    }
}

// ---------------- aggregation ------------------------------------------------
__global__ void __launch_bounds__(256) aggregate_kernel(
    const float* __restrict__ ln2g, const float* __restrict__ ln2b,
    const float* __restrict__ w2w, const float* __restrict__ w2b, int lyr)
{
    int n = blockIdx.x;
    int tid = threadIdx.x;
    __shared__ float ws[128];
    __shared__ int ss[128];
    __shared__ float nc[6];
    const float* c0 = g_c0 + lyr * 4;
    const float* c1 = g_c1 + lyr * 4;
    int beg = g_rowptr[n], end = g_rowptr[n + 1];
    if (tid == 0) {
        nc[0] = g_S[n]; nc[1] = g_Q[n];
        float4 u = g_ud[n];
        nc[2] = u.x; nc[3] = u.y; nc[4] = u.z; nc[5] = u.w;
    }
    __syncthreads();
    float acc = 0.0f;
    for (int e0 = beg; e0 < end; e0 += 128) {
        int cnt = min(128, end - e0);
        if (tid < cnt) {
            int srcn = g_csrc[e0 + tid];
            float4 us = g_us[srcn];
            float mu = (g_S[srcn] + nc[0]) * INV_ED;
            float var = fmaf(-mu, mu, (g_Q[srcn] + nc[1]) * INV_ED);
            float rs = rsqrtf(var + LNEPS);
            float t0 = gelu_f(fmaf(rs, (us.x + nc[2]) - mu * c1[0], c0[0]));
            float t1 = gelu_f(fmaf(rs, (us.y + nc[3]) - mu * c1[1], c0[1]));
            float t2 = gelu_f(fmaf(rs, (us.z + nc[4]) - mu * c1[2], c0[2]));
            float t3 = gelu_f(fmaf(rs, (us.w + nc[5]) - mu * c1[3], c0[3]));
            float mu2 = 0.25f * (t0 + t1 + t2 + t3);
            float d0 = t0 - mu2, d1 = t1 - mu2, d2 = t2 - mu2, d3 = t3 - mu2;
            float var2 = 0.25f * (d0 * d0 + d1 * d1 + d2 * d2 + d3 * d3);
            float rs2 = rsqrtf(var2 + LNEPS);
            float z = (fmaf(d0 * rs2, ln2g[0], ln2b[0])) * w2w[0]
                    + (fmaf(d1 * rs2, ln2g[1], ln2b[1])) * w2w[1]
                    + (fmaf(d2 * rs2, ln2g[2], ln2b[2])) * w2w[2]
                    + (fmaf(d3 * rs2, ln2g[3], ln2b[3])) * w2w[3] + w2b[0];
            ws[tid] = 1.0f / (1.0f + expf(-z));
            ss[tid] = srcn;
        }
        __syncthreads();
        #pragma unroll 4
        for (int i = 0; i < cnt; i++)
            acc = fmaf(g_m[(size_t)ss[i] * CC + tid], ws[i], acc);
        __syncthreads();
    }
    size_t o = (size_t)n * CC + tid;
    __nv_bfloat16 hi = __float2bfloat16(acc);
    g_aghi[o] = hi;
    g_aglo[o] = __float2bfloat16(acc - __bfloat162float(hi));
}

// ---------------- pooling + head --------------------------------------------
__global__ void __launch_bounds__(256) pool_kernel(
    const int* __restrict__ batch, const float* __restrict__ head_w)
{
    int n = (blockIdx.x * blockDim.x + threadIdx.x) >> 5;
    int lane = threadIdx.x & 31;
    if (n >= NN) return;
    const float* hr = g_h + (size_t)n * CC;
    float s = 0;
    #pragma unroll
    for (int j = 0; j < 8; j++)
        s = fmaf(hr[lane + j * 32], head_w[lane + j * 32], s);
    #pragma unroll
    for (int off = 16; off; off >>= 1)
        s += __shfl_xor_sync(0xffffffffu, s, off);
    if (lane == 0) atomicAdd(&g_pool[batch[n]], s);
}
__global__ void final_kernel(float* __restrict__ out, const float* __restrict__ head_b) {
    int g = threadIdx.x;
    if (g < NG)
        out[g] = g_pool[g] / fmaxf((float)g_gcnt[g], 1.0f) + head_b[0];
}

// ---------------- launch -----------------------------------------------------
extern "C" void kernel_launch(void* const* d_in, const int* in_sizes, int n_in,
                              void* d_out, int out_size)
{
    const float* x       = (const float*)d_in[0];
    const float* xpos    = (const float*)d_in[1];
    const int*   ei      = (const int*)  d_in[2];
    const int*   batch   = (const int*)  d_in[3];
    const float* dense_w = (const float*)d_in[4];
    const float* dense_b = (const float*)d_in[5];
    const float* d1_w    = (const float*)d_in[6];
    const float* d1_b    = (const float*)d_in[7];
    const float* ln1_g   = (const float*)d_in[8];
    const float* ln1_b   = (const float*)d_in[9];
    const float* w1_w    = (const float*)d_in[10];
    const float* w1_b    = (const float*)d_in[11];
    const float* ln2_g   = (const float*)d_in[12];
    const float* ln2_b   = (const float*)d_in[13];
    const float* w2_w    = (const float*)d_in[14];
    const float* w2_b    = (const float*)d_in[15];
    const float* d2_w    = (const float*)d_in[16];
    const float* d2_b    = (const float*)d_in[17];
    const float* head_w  = (const float*)d_in[18];
    const float* head_b  = (const float*)d_in[19];

    const int* src = ei;
    const int* dst = ei + NE;

    cudaFuncSetAttribute(gemm_mma_kernel, cudaFuncAttributeMaxDynamicSharedMemorySize, GEMM_SMEM);

    float* p_h;  cudaGetSymbolAddress((void**)&p_h,  g_h);
    float* p_m;  cudaGetSymbolAddress((void**)&p_m,  g_m);
    __nv_bfloat16 *p_xhi, *p_xlo, *p_hhi, *p_hlo, *p_aghi, *p_aglo, *p_wthi, *p_wtlo;
    cudaGetSymbolAddress((void**)&p_xhi, g_xhi);
    cudaGetSymbolAddress((void**)&p_xlo, g_xlo);
    cudaGetSymbolAddress((void**)&p_hhi, g_hhi);
    cudaGetSymbolAddress((void**)&p_hlo, g_hlo);
    cudaGetSymbolAddress((void**)&p_aghi, g_aghi);
    cudaGetSymbolAddress((void**)&p_aglo, g_aglo);
    cudaGetSymbolAddress((void**)&p_wthi, g_wthi);
    cudaGetSymbolAddress((void**)&p_wtlo, g_wtlo);

    dim3 ggrid(4, (NN + 127) / 128);   // 4 x 157 = 628 CTAs (N split in 64s)

    conv_all_kernel<<<(NX + WT_SZ + 255) / 256, 256>>>(x, dense_w, d1_w, d2_w);
    const_all_kernel<<<NL, 544>>>(ln1_g, ln1_b, w1_w, w1_b);
    init_stats_kernel<<<(NN + 255) / 256, 256>>>(xpos, 0);
    // h = x @ dense_w + b (no act, split out, no stats)
    gemm_mma_kernel<<<ggrid, 256, GEMM_SMEM>>>(
        p_xhi, p_xlo, p_wthi + WT_DENSE, p_wtlo + WT_DENSE,
        dense_b, p_h, p_hhi, p_hlo, NN, KXP, KXP / 32, 0, 0, 0);
    // m = gelu(h @ d1_w + b), stats fused (layer 0)
    gemm_mma_kernel<<<ggrid, 256, GEMM_SMEM>>>(
        p_hhi, p_hlo, p_wthi + 256 * KXP, p_wtlo + 256 * KXP,
        d1_b, p_m, nullptr, nullptr, NN, CC, CC / 32, 1, 0, 1);

    // CSR build + batch counts (needed before first aggregate)
    zero_kernel<<<(NN + 255) / 256, 256>>>();
    hist2_kernel<<<(NE + 255) / 256, 256>>>(dst, batch);
    scan1_kernel<<<20, 1024>>>();
    scan2_kernel<<<1, 1>>>();
    scan3_kernel<<<(NN + 255) / 256, 256>>>();
    fill_kernel<<<(NE + 255) / 256, 256>>>(src, dst);

    for (int l = 0; l < NL; l++) {
        size_t wd1 = (size_t)256 * KXP + (size_t)(2 * l) * 65536;
        size_t wd2 = (size_t)256 * KXP + (size_t)(2 * l + 1) * 65536;
        if (l > 0) {
            gemm_mma_kernel<<<ggrid, 256, GEMM_SMEM>>>(
                p_hhi, p_hlo, p_wthi + wd1, p_wtlo + wd1,
                d1_b + l * CC, p_m, nullptr, nullptr, NN, CC, CC / 32, 1, l, 1);
        }
        aggregate_kernel<<<NN, 256>>>(ln2_g + l * 4, ln2_b + l * 4,
                                      w2_w + l * 4, w2_b + l, l);
        if (l + 1 < NL)
            init_stats_kernel<<<(NN + 255) / 256, 256>>>(xpos, l + 1);
        gemm_mma_kernel<<<ggrid, 256, GEMM_SMEM>>>(
            p_aghi, p_aglo, p_wthi + wd2, p_wtlo + wd2,
            d2_b + l * CC, p_h, p_hhi, p_hlo, NN, CC, CC / 32, 1, 0, 0);
    }

    pool_kernel<<<(NN * 32 + 255) / 256, 256>>>(batch, head_w);
    final_kernel<<<1, 32>>>((float*)d_out, head_b);
}